// round 7
// baseline (speedup 1.0000x reference)
#include <cuda_runtime.h>
#include <cuda_bf16.h>
#include <math.h>
#include <cstdint>

#define BATCH 1024
#define D     64
#define VOC   50000
#define NREL  7
#define KC    2240      // folded compose K: 2080 tri + 128 linear + 32 pad
#define NCHC  70
#define KF    4224      // final K: 4096 kron + 128 linear
#define NCHF  132

// smem word/byte layout
#define SO_IDX 0           // 3 x 256 B idx slots
#define SO_T   1024        // T[130][128] f32 = 66560 B
#define SO_A   67584       // 2 x (16 k2 x 136) words = 17408 B
#define SO_W   84992       // 3 x (16 k2 x 72) words = 13824 B
#define SMEM_BYTES 98816
#define AP 136             // A pitch (words per k2 row)
#define WP 72              // W pitch

// -------- device scratch --------
__device__ float    g_vocT[VOC * D];
__device__ float    g_XA[2 * BATCH * 64 * D];
__device__ float    g_XB[2 * BATCH * 32 * D];
__device__ uint32_t g_Wc2[NCHC * 1024];   // bf16x2 compose W chunks [c][k2*64+e]
__device__ uint32_t g_Wf2[NCHF * 1024];   // bf16x2 final W chunks
__device__ int      g_idxC[KC * 2];       // per k: (a_off, b_off) byte offsets into T
__device__ int      g_idxF[KF * 2];
__device__ float    g_bc[D];
__device__ float    g_bf[D];
__device__ float    g_part[160 * 8192];

// -------- PTX helpers --------
__device__ __forceinline__ uint32_t s2u(const void* p) {
    uint32_t a;
    asm("{.reg .u64 t; cvta.to.shared.u64 t, %1; cvt.u32.u64 %0, t;}" : "=r"(a) : "l"(p));
    return a;
}
__device__ __forceinline__ void mma16(float* d, const uint32_t* a, uint32_t b0, uint32_t b1) {
    asm volatile(
        "mma.sync.aligned.m16n8k16.row.col.f32.bf16.bf16.f32 "
        "{%0,%1,%2,%3},{%4,%5,%6,%7},{%8,%9},{%0,%1,%2,%3};"
        : "+f"(d[0]), "+f"(d[1]), "+f"(d[2]), "+f"(d[3])
        : "r"(a[0]), "r"(a[1]), "r"(a[2]), "r"(a[3]), "r"(b0), "r"(b1));
}
__device__ __forceinline__ uint32_t pack_bf16(float lo, float hi) {
    uint32_t d;
    asm("cvt.rn.bf16x2.f32 %0, %1, %2;" : "=r"(d) : "f"(hi), "f"(lo));
    return d;
}
#define CPA16(dst, src) \
    asm volatile("cp.async.ca.shared.global [%0], [%1], 16;" :: "r"(dst), "l"(src))
#define CPCOMMIT() asm volatile("cp.async.commit_group;")
#define CPWAIT(n)  asm volatile("cp.async.wait_group %0;" :: "n"(n) : "memory")

// -------- vocab transpose: (64, 50000) -> (50000, 64) --------
__global__ void k_transpose_voc(const float* __restrict__ voc_w) {
    __shared__ float tile[64][65];
    int v0 = blockIdx.x * 64;
    for (int idx = threadIdx.x; idx < 64 * 64; idx += 256) {
        int d = idx >> 6, vv = idx & 63;
        int v = v0 + vv;
        tile[vv][d] = (v < VOC) ? voc_w[d * VOC + v] : 0.f;
    }
    __syncthreads();
    for (int idx = threadIdx.x; idx < 64 * 64; idx += 256) {
        int vv = idx >> 6, d = idx & 63;
        int v = v0 + vv;
        if (v < VOC) g_vocT[v * D + d] = tile[vv][d];
    }
}

// -------- weight/index prep --------
__device__ __forceinline__ int tri_i_of_k(int k) {
    int i = (int)floorf((sqrtf(8.f * (float)k + 1.f) - 1.f) * 0.5f);
    while ((i + 1) * (i + 2) / 2 <= k) i++;
    while (i * (i + 1) / 2 > k) i--;
    return i;
}
__device__ __forceinline__ float foldc(const float* cpst_w, const float* cps_w, int k, int e) {
    if (k < 2080) {
        int i = tri_i_of_k(k);
        int j = k - i * (i + 1) / 2;
        return (j < i) ? cpst_w[e * 4096 + i * 64 + j] + cpst_w[e * 4096 + j * 64 + i]
                       : cpst_w[e * 4096 + i * 65];
    } else if (k < 2208) {
        return cps_w[e * 128 + (k - 2080)];
    }
    return 0.f;
}
__global__ void k_prep(const float* __restrict__ cps_w,  const float* __restrict__ cps_b,
                       const float* __restrict__ cpst_w, const float* __restrict__ cpst_b,
                       const float* __restrict__ cpr_w,  const float* __restrict__ cpr_b,
                       const float* __restrict__ cprt_w, const float* __restrict__ cprt_b) {
    int blk = blockIdx.x, t = threadIdx.x;
    if (blk < NCHC) {                        // compose W chunks, bf16x2 [k2][e]
        int c = blk;
        for (int u = t; u < 1024; u += 256) {
            int e = u & 63, k2 = u >> 6;
            int k = c * 32 + 2 * k2;
            float v0 = foldc(cpst_w, cps_w, k, e);
            float v1 = foldc(cpst_w, cps_w, k + 1, e);
            g_Wc2[c * 1024 + u] = pack_bf16(v0, v1);
        }
    } else if (blk < NCHC + NCHF) {          // final W chunks
        int c = blk - NCHC;
        for (int u = t; u < 1024; u += 256) {
            int e = u & 63, k2 = u >> 6;
            int k = c * 32 + 2 * k2;
            float v0 = (k < 4096) ? cprt_w[e * 4096 + k] : cpr_w[e * 128 + (k - 4096)];
            float v1 = (k + 1 < 4096) ? cprt_w[e * 4096 + k + 1] : cpr_w[e * 128 + (k + 1 - 4096)];
            g_Wf2[c * 1024 + u] = pack_bf16(v0, v1);
        }
    } else if (blk == NCHC + NCHF) {         // biases
        if (t < D) {
            g_bc[t] = cps_b[t] + cpst_b[t];
            g_bf[t] = cpr_b[t] + cprt_b[t];
        }
    } else if (blk == NCHC + NCHF + 1) {     // compose idx: byte offsets
        for (int k = t; k < KC; k += 256) {
            int a, b2;
            if (k < 2080) { int i = tri_i_of_k(k); a = i; b2 = k - i * (i + 1) / 2; }
            else if (k < 2208) { a = k - 2080; b2 = 128; }
            else { a = 129; b2 = 129; }
            g_idxC[k * 2] = a * 512;
            g_idxC[k * 2 + 1] = b2 * 512;
        }
    } else {                                 // final idx
        for (int k = t; k < KF; k += 256) {
            int a, b2;
            if (k < 4096) { a = k >> 6; b2 = 64 + (k & 63); }
            else { a = k - 4096; b2 = 128; }
            g_idxF[k * 2] = a * 512;
            g_idxF[k * 2 + 1] = b2 * 512;
        }
    }
}

// -------- pipelined bf16 tensor GEMM level --------
// mode: 0 compose, 1 final, 2 level1 (fused vocab gather)
__global__ void __launch_bounds__(256, 2) k_gemm(const float* __restrict__ Xin,
                                                 float* __restrict__ Xout,
                                                 float* __restrict__ part,
                                                 const uint32_t* __restrict__ Wq,
                                                 const int* __restrict__ idx,
                                                 const float* __restrict__ bias,
                                                 const int* __restrict__ left,
                                                 const int* __restrict__ right,
                                                 const float* __restrict__ voc_b,
                                                 int n_out, int nchunks, int split,
                                                 int ntiles, int mode) {
    extern __shared__ char smem[];
    const uint32_t sbase = s2u(smem);
    float* T = (float*)(smem + SO_T);
    uint32_t* As = (uint32_t*)(smem + SO_A);
    uint32_t* Ws = (uint32_t*)(smem + SO_W);
    const int t = threadIdx.x;
    const int s = blockIdx.x % split;
    const int tile = blockIdx.x / split;
    const int cpb = nchunks / split;
    const int c0 = s * cpb, c1 = c0 + cpb;

    // ---- stage helper (macro-hygienic: single statement) ----
#define STAGE(c)                                                                     \
    do {                                                                             \
        int _slot = (c) % 3;                                                         \
        uint32_t _wd = sbase + SO_W +                                                \
            (uint32_t)(_slot * 1152 + (t >> 4) * WP + (t & 15) * 4) * 4;             \
        CPA16(_wd, Wq + (size_t)(c) * 1024 + t * 4);                                 \
        if (t < 16)                                                                  \
            CPA16(sbase + SO_IDX + _slot * 256 + t * 16, idx + (c) * 64 + t * 4);    \
        CPCOMMIT();                                                                  \
    } while (0)

    STAGE(c0);
    if (c0 + 1 < c1) {
        STAGE(c0 + 1);
    } else {
        CPCOMMIT();
    }

    // ---- load L/R into T[feature][m] + ones/zeros rows ----
    {
        int m = t >> 1, half = t & 1;
        const float* src;
        if (mode == 1) {
            src = Xin + (size_t)(half * BATCH + tile * 128 + m) * D;
        } else if (mode == 2) {
            int g = tile * 128 + m;
            int p = g & 31, bp = g >> 5;               // n_out = 32
            int tree = bp >> 10, b = bp & 1023;
            int leaf = 2 * p + half;
            int vidx = tree ? __ldg(right + b * 64 + leaf) : __ldg(left + b * 64 + leaf);
            src = g_vocT + (size_t)vidx * D;
        } else {
            int g = tile * 128 + m;
            int p = g % n_out, bp = g / n_out;
            src = Xin + (size_t)(bp * 2 * n_out + 2 * p + half) * D;
        }
        float* dT = T + (half * 64) * 128 + m;
        if (mode == 2) {
#pragma unroll
            for (int it = 0; it < 16; it++) {
                int f = it * 4;
                float4 v = *(const float4*)(src + f);
                float4 bb = *(const float4*)(voc_b + f);
                dT[f * 128] = v.x + bb.x; dT[(f + 1) * 128] = v.y + bb.y;
                dT[(f + 2) * 128] = v.z + bb.z; dT[(f + 3) * 128] = v.w + bb.w;
            }
        } else {
#pragma unroll
            for (int it = 0; it < 16; it++) {
                int f = it * 4;
                float4 v = *(const float4*)(src + f);
                dT[f * 128] = v.x; dT[(f + 1) * 128] = v.y;
                dT[(f + 2) * 128] = v.z; dT[(f + 3) * 128] = v.w;
            }
        }
        if (t < 128) { T[128 * 128 + t] = 1.f; T[129 * 128 + t] = 0.f; }
    }

    const int l = t & 31, wid = t >> 5;
    const int qr = l >> 2, qc = l & 3;
    const int m0 = (wid & 3) * 32;
    const int n0 = (wid >> 2) * 32;
    const int mloc = t & 127;
    const int kh2 = (t >> 7) * 8;
    const char* Tm = (const char*)T + mloc * 4;

    float acc[2][4][4] = {};

    // ---- A-gen helper ----
#define AGEN(c)                                                                      \
    do {                                                                             \
        const int4* ix = (const int4*)(smem + SO_IDX + ((c) % 3) * 256) + kh2;       \
        uint32_t* Ad = As + ((c) & 1) * (16 * AP) + mloc;                            \
        _Pragma("unroll")                                                            \
        for (int q = 0; q < 8; q++) {                                                \
            int4 p = ix[q];                                                          \
            float v0 = *(const float*)(Tm + p.x) * *(const float*)(Tm + p.y);        \
            float v1 = *(const float*)(Tm + p.z) * *(const float*)(Tm + p.w);        \
            Ad[(kh2 + q) * AP] = pack_bf16(v0, v1);                                  \
        }                                                                            \
    } while (0)

    CPWAIT(1);
    __syncthreads();
    AGEN(c0);

    for (int c = c0; c < c1; c++) {
        CPWAIT(0);
        __syncthreads();    // A(c) visible; prior MMA/W reads complete
        if (c + 2 < c1) STAGE(c + 2);
        if (c + 1 < c1) AGEN(c + 1);

        const uint32_t* Ab = As + (c & 1) * (16 * AP);
        const uint32_t* Wb = Ws + (c % 3) * 1152;
#pragma unroll
        for (int ks = 0; ks < 2; ks++) {
            const uint32_t* ap = Ab + (ks * 8 + qc) * AP;
            uint32_t af[2][4];
#pragma unroll
            for (int mf = 0; mf < 2; mf++) {
                int r = m0 + mf * 16 + qr;
                af[mf][0] = ap[r];
                af[mf][1] = ap[r + 8];
                af[mf][2] = ap[4 * AP + r];
                af[mf][3] = ap[4 * AP + r + 8];
            }
            const uint32_t* bp = Wb + (ks * 8 + qc) * WP + n0 + qr;
#pragma unroll
            for (int nf = 0; nf < 4; nf++) {
                uint32_t b0 = bp[nf * 8];
                uint32_t b1 = bp[4 * WP + nf * 8];
                mma16(acc[0][nf], af[0], b0, b1);
                mma16(acc[1][nf], af[1], b0, b1);
            }
        }
    }

    // ---- epilogue ----
#pragma unroll
    for (int mf = 0; mf < 2; mf++) {
#pragma unroll
        for (int nf = 0; nf < 4; nf++) {
            int row = m0 + mf * 16 + qr;
            int col = n0 + nf * 8 + qc * 2;
            float* a4 = acc[mf][nf];
            if (split == 1) {
                float b0v = __ldg(bias + col), b1v = __ldg(bias + col + 1);
                float* dst = Xout + (size_t)(tile * 128 + row) * D + col;
                *(float2*)dst = make_float2(tanhf(a4[0] + b0v), tanhf(a4[1] + b1v));
                dst += 8 * D;
                *(float2*)dst = make_float2(tanhf(a4[2] + b0v), tanhf(a4[3] + b1v));
            } else {
                float* dst = part + (size_t)(s * ntiles + tile) * 8192 + row * 64 + col;
                *(float2*)dst = make_float2(a4[0], a4[1]);
                *(float2*)(dst + 8 * 64) = make_float2(a4[2], a4[3]);
            }
        }
    }
#undef STAGE
#undef AGEN
}

// -------- sum K-split partials + bias + tanh --------
__global__ void __launch_bounds__(256) k_reduce(const float* __restrict__ part,
                                                float* __restrict__ Xout,
                                                const float* __restrict__ bias,
                                                int ntiles, int split) {
    int tile = blockIdx.x;
    for (int idx = threadIdx.x; idx < 8192; idx += 256) {
        float sum = 0.f;
        for (int s = 0; s < split; s++) sum += part[(size_t)(s * ntiles + tile) * 8192 + idx];
        Xout[(size_t)tile * 8192 + idx] = tanhf(sum + bias[idx & 63]);
    }
}

// -------- final epilogue: reduce + bias + leaky + logits + softmax --------
__global__ void __launch_bounds__(256) k_final_reduce(const float* __restrict__ part,
                                                      float* __restrict__ out,
                                                      const float* __restrict__ bias,
                                                      const float* __restrict__ sm_w,
                                                      const float* __restrict__ sm_b,
                                                      int split) {
    __shared__ float actT[64 * 132];
    const int tile = blockIdx.x;
    const int t = threadIdx.x;
    const int ntiles = BATCH / 128;

    for (int idx = t; idx < 8192; idx += 256) {
        float sum = 0.f;
        for (int s = 0; s < split; s++) sum += part[(size_t)(s * ntiles + tile) * 8192 + idx];
        sum += bias[idx & 63];
        sum = (sum > 0.f) ? sum : 0.01f * sum;
        actT[(idx & 63) * 132 + (idx >> 6)] = sum;
    }
    __syncthreads();

    if (t < 128) {
        int m = t;
        float lg[NREL];
#pragma unroll
        for (int c = 0; c < NREL; c++) {
            float ssum = sm_b[c];
#pragma unroll 8
            for (int e = 0; e < 64; e++) ssum += actT[e * 132 + m] * sm_w[c * 64 + e];
            lg[c] = ssum;
        }
        float mx = lg[0];
#pragma unroll
        for (int c = 1; c < NREL; c++) mx = fmaxf(mx, lg[c]);
        float sum = 0.f;
#pragma unroll
        for (int c = 0; c < NREL; c++) { lg[c] = expf(lg[c] - mx); sum += lg[c]; }
        float inv = 1.f / sum;
#pragma unroll
        for (int c = 0; c < NREL; c++) out[(tile * 128 + m) * NREL + c] = lg[c] * inv;
    }
}

// -------- launcher --------
extern "C" void kernel_launch(void* const* d_in, const int* in_sizes, int n_in,
                              void* d_out, int out_size) {
    (void)in_sizes; (void)n_in; (void)out_size;
    const int*   left   = (const int*)d_in[0];
    const int*   right  = (const int*)d_in[1];
    const float* voc_w  = (const float*)d_in[2];
    const float* voc_b  = (const float*)d_in[3];
    const float* cps_w  = (const float*)d_in[4];
    const float* cps_b  = (const float*)d_in[5];
    const float* cpst_w = (const float*)d_in[6];
    const float* cpst_b = (const float*)d_in[7];
    const float* cpr_w  = (const float*)d_in[8];
    const float* cpr_b  = (const float*)d_in[9];
    const float* cprt_w = (const float*)d_in[10];
    const float* cprt_b = (const float*)d_in[11];
    const float* sm_w   = (const float*)d_in[12];
    const float* sm_b   = (const float*)d_in[13];
    float* out = (float*)d_out;

    float *XA, *XB, *bc, *bf, *part;
    uint32_t *Wc2, *Wf2;
    int *idxC, *idxF;
    cudaGetSymbolAddress((void**)&XA, g_XA);
    cudaGetSymbolAddress((void**)&XB, g_XB);
    cudaGetSymbolAddress((void**)&Wc2, g_Wc2);
    cudaGetSymbolAddress((void**)&Wf2, g_Wf2);
    cudaGetSymbolAddress((void**)&bc, g_bc);
    cudaGetSymbolAddress((void**)&bf, g_bf);
    cudaGetSymbolAddress((void**)&part, g_part);
    cudaGetSymbolAddress((void**)&idxC, g_idxC);
    cudaGetSymbolAddress((void**)&idxF, g_idxF);

    cudaFuncSetAttribute(k_gemm, cudaFuncAttributeMaxDynamicSharedMemorySize, SMEM_BYTES);

    k_transpose_voc<<<(VOC + 63) / 64, 256>>>(voc_w);
    k_prep<<<NCHC + NCHF + 3, 256>>>(cps_w, cps_b, cpst_w, cpst_b,
                                     cpr_w, cpr_b, cprt_w, cprt_b);

    // level 1 (fused vocab gather): 512 tiles
    k_gemm<<<512, 256, SMEM_BYTES>>>(nullptr, XB, part, Wc2, idxC, bc,
                                     left, right, voc_b, 32, NCHC, 1, 512, 2);
    // levels 2..3
    k_gemm<<<256, 256, SMEM_BYTES>>>(XB, XA, part, Wc2, idxC, bc,
                                     left, right, voc_b, 16, NCHC, 1, 256, 0);
    k_gemm<<<128, 256, SMEM_BYTES>>>(XA, XB, part, Wc2, idxC, bc,
                                     left, right, voc_b, 8, NCHC, 1, 128, 0);
    // level 4: 64 tiles, split 2
    k_gemm<<<128, 256, SMEM_BYTES>>>(XB, XA, part, Wc2, idxC, bc,
                                     left, right, voc_b, 4, NCHC, 2, 64, 0);
    k_reduce<<<64, 256>>>(part, XA, bc, 64, 2);
    // level 5: 32 tiles, split 5
    k_gemm<<<160, 256, SMEM_BYTES>>>(XA, XB, part, Wc2, idxC, bc,
                                     left, right, voc_b, 2, NCHC, 5, 32, 0);
    k_reduce<<<32, 256>>>(part, XB, bc, 32, 5);
    // level 6: 16 tiles, split 7
    k_gemm<<<112, 256, SMEM_BYTES>>>(XB, XA, part, Wc2, idxC, bc,
                                     left, right, voc_b, 1, NCHC, 7, 16, 0);
    k_reduce<<<16, 256>>>(part, XA, bc, 16, 7);
    // final: 8 tiles, split 12
    k_gemm<<<96, 256, SMEM_BYTES>>>(XA, XB, part, Wf2, idxF, bf,
                                    left, right, voc_b, 1, NCHF, 12, 8, 1);
    k_final_reduce<<<BATCH / 128, 256>>>(part, out, bf, sm_w, sm_b, 12);
}

// round 8
// speedup vs baseline: 1.3297x; 1.3297x over previous
#include <cuda_runtime.h>
#include <cuda_bf16.h>
#include <math.h>
#include <cstdint>

#define BATCH 1024
#define D     64
#define VOC   50000
#define NREL  7
#define KC    2240      // folded compose K: 2080 tri + 128 linear + 32 pad
#define NCHC  70
#define KF    4224      // final K: 4096 kron + 128 linear
#define NCHF  132

// smem byte layout (total 64 KB -> 3 CTAs/SM)
#define SO_IDX 0           // 3 x 256 B idx slots
#define SO_T   1024        // T bf16 [130 f][128 m] = 33280 B
#define SO_A   34304       // 2 x (16 k2 x 136) words = 17408 B
#define SO_W   51712       // 3 x (16 k2 x 72) words = 13824 B
#define SMEM_BYTES 65536
#define AP 136             // A pitch (words per k2 row)
#define WP 72              // W pitch

// -------- device scratch --------
__device__ float    g_vocT[VOC * D];
__device__ float    g_XA[2 * BATCH * 64 * D];
__device__ float    g_XB[2 * BATCH * 32 * D];
__device__ uint32_t g_Wc2[NCHC * 1024];   // bf16x2 compose W chunks [c][k2*64+e]
__device__ uint32_t g_Wf2[NCHF * 1024];   // bf16x2 final W chunks
__device__ int      g_idxC[KC * 2];       // per k: (a_off, b_off) byte offsets into T
__device__ int      g_idxF[KF * 2];
__device__ float    g_bc[D];
__device__ float    g_bf[D];
__device__ float    g_part[512 * 8192];   // K-split partials (16.8 MB)

// -------- PTX helpers --------
__device__ __forceinline__ uint32_t s2u(const void* p) {
    uint32_t a;
    asm("{.reg .u64 t; cvta.to.shared.u64 t, %1; cvt.u32.u64 %0, t;}" : "=r"(a) : "l"(p));
    return a;
}
__device__ __forceinline__ void mma16(float* d, const uint32_t* a, uint32_t b0, uint32_t b1) {
    asm volatile(
        "mma.sync.aligned.m16n8k16.row.col.f32.bf16.bf16.f32 "
        "{%0,%1,%2,%3},{%4,%5,%6,%7},{%8,%9},{%0,%1,%2,%3};"
        : "+f"(d[0]), "+f"(d[1]), "+f"(d[2]), "+f"(d[3])
        : "r"(a[0]), "r"(a[1]), "r"(a[2]), "r"(a[3]), "r"(b0), "r"(b1));
}
__device__ __forceinline__ uint32_t pack_bf16(float lo, float hi) {
    uint32_t d;
    asm("cvt.rn.bf16x2.f32 %0, %1, %2;" : "=r"(d) : "f"(hi), "f"(lo));
    return d;
}
#define CPA16(dst, src) \
    asm volatile("cp.async.ca.shared.global [%0], [%1], 16;" :: "r"(dst), "l"(src))
#define CPCOMMIT() asm volatile("cp.async.commit_group;")
#define CPWAIT(n)  asm volatile("cp.async.wait_group %0;" :: "n"(n) : "memory")

// -------- vocab transpose: (64, 50000) -> (50000, 64) --------
__global__ void k_transpose_voc(const float* __restrict__ voc_w) {
    __shared__ float tile[64][65];
    int v0 = blockIdx.x * 64;
    for (int idx = threadIdx.x; idx < 64 * 64; idx += 256) {
        int d = idx >> 6, vv = idx & 63;
        int v = v0 + vv;
        tile[vv][d] = (v < VOC) ? voc_w[d * VOC + v] : 0.f;
    }
    __syncthreads();
    for (int idx = threadIdx.x; idx < 64 * 64; idx += 256) {
        int vv = idx >> 6, d = idx & 63;
        int v = v0 + vv;
        if (v < VOC) g_vocT[v * D + d] = tile[vv][d];
    }
}

// -------- weight/index prep --------
__device__ __forceinline__ int tri_i_of_k(int k) {
    int i = (int)floorf((sqrtf(8.f * (float)k + 1.f) - 1.f) * 0.5f);
    while ((i + 1) * (i + 2) / 2 <= k) i++;
    while (i * (i + 1) / 2 > k) i--;
    return i;
}
__device__ __forceinline__ float foldc(const float* cpst_w, const float* cps_w, int k, int e) {
    if (k < 2080) {
        int i = tri_i_of_k(k);
        int j = k - i * (i + 1) / 2;
        return (j < i) ? cpst_w[e * 4096 + i * 64 + j] + cpst_w[e * 4096 + j * 64 + i]
                       : cpst_w[e * 4096 + i * 65];
    } else if (k < 2208) {
        return cps_w[e * 128 + (k - 2080)];
    }
    return 0.f;
}
__global__ void k_prep(const float* __restrict__ cps_w,  const float* __restrict__ cps_b,
                       const float* __restrict__ cpst_w, const float* __restrict__ cpst_b,
                       const float* __restrict__ cpr_w,  const float* __restrict__ cpr_b,
                       const float* __restrict__ cprt_w, const float* __restrict__ cprt_b) {
    int blk = blockIdx.x, t = threadIdx.x;
    if (blk < NCHC) {                        // compose W chunks, bf16x2 [k2][e]
        int c = blk;
        for (int u = t; u < 1024; u += 256) {
            int e = u & 63, k2 = u >> 6;
            int k = c * 32 + 2 * k2;
            float v0 = foldc(cpst_w, cps_w, k, e);
            float v1 = foldc(cpst_w, cps_w, k + 1, e);
            g_Wc2[c * 1024 + u] = pack_bf16(v0, v1);
        }
    } else if (blk < NCHC + NCHF) {          // final W chunks
        int c = blk - NCHC;
        for (int u = t; u < 1024; u += 256) {
            int e = u & 63, k2 = u >> 6;
            int k = c * 32 + 2 * k2;
            float v0 = (k < 4096) ? cprt_w[e * 4096 + k] : cpr_w[e * 128 + (k - 4096)];
            float v1 = (k + 1 < 4096) ? cprt_w[e * 4096 + k + 1] : cpr_w[e * 128 + (k + 1 - 4096)];
            g_Wf2[c * 1024 + u] = pack_bf16(v0, v1);
        }
    } else if (blk == NCHC + NCHF) {         // biases
        if (t < D) {
            g_bc[t] = cps_b[t] + cpst_b[t];
            g_bf[t] = cpr_b[t] + cprt_b[t];
        }
    } else if (blk == NCHC + NCHF + 1) {     // compose idx: byte offsets (T row = 256 B)
        for (int k = t; k < KC; k += 256) {
            int a, b2;
            if (k < 2080) { int i = tri_i_of_k(k); a = i; b2 = k - i * (i + 1) / 2; }
            else if (k < 2208) { a = k - 2080; b2 = 128; }
            else { a = 129; b2 = 129; }
            g_idxC[k * 2] = a * 256;
            g_idxC[k * 2 + 1] = b2 * 256;
        }
    } else {                                 // final idx
        for (int k = t; k < KF; k += 256) {
            int a, b2;
            if (k < 4096) { a = k >> 6; b2 = 64 + (k & 63); }
            else { a = k - 4096; b2 = 128; }
            g_idxF[k * 2] = a * 256;
            g_idxF[k * 2 + 1] = b2 * 256;
        }
    }
}

// -------- pipelined bf16 tensor GEMM level --------
// mode: 0 compose, 1 final, 2 level1 (fused vocab gather)
__global__ void __launch_bounds__(256, 3) k_gemm(const float* __restrict__ Xin,
                                                 float* __restrict__ Xout,
                                                 float* __restrict__ part,
                                                 const uint32_t* __restrict__ Wq,
                                                 const int* __restrict__ idx,
                                                 const float* __restrict__ bias,
                                                 const int* __restrict__ left,
                                                 const int* __restrict__ right,
                                                 const float* __restrict__ voc_b,
                                                 int n_out, int nchunks, int split,
                                                 int ntiles, int mode) {
    extern __shared__ char smem[];
    const uint32_t sbase = s2u(smem);
    uint32_t* Tw = (uint32_t*)(smem + SO_T);      // bf16 pairs: word f*64 + m/2
    uint32_t* As = (uint32_t*)(smem + SO_A);
    uint32_t* Ws = (uint32_t*)(smem + SO_W);
    const int t = threadIdx.x;
    const int s = blockIdx.x % split;
    const int tile = blockIdx.x / split;
    const int cpb = nchunks / split;
    const int c0 = s * cpb, c1 = c0 + cpb;

#define STAGE(c)                                                                     \
    do {                                                                             \
        int _slot = (c) % 3;                                                         \
        uint32_t _wd = sbase + SO_W +                                                \
            (uint32_t)(_slot * 1152 + (t >> 4) * WP + (t & 15) * 4) * 4;             \
        CPA16(_wd, Wq + (size_t)(c) * 1024 + t * 4);                                 \
        if (t < 16)                                                                  \
            CPA16(sbase + SO_IDX + _slot * 256 + t * 16, idx + (c) * 64 + t * 4);    \
        CPCOMMIT();                                                                  \
    } while (0)

    STAGE(c0);
    if (c0 + 1 < c1) {
        STAGE(c0 + 1);
    } else {
        CPCOMMIT();
    }

    // ---- load L/R into T (bf16, m-pairs packed) + ones/zeros rows ----
    {
        int mp = t & 63, half = (t >> 6) & 1, fb = (t >> 7) * 32;
        int m0 = 2 * mp;
        const float *s0, *s1;
        if (mode == 1) {
            s0 = Xin + (size_t)(half * BATCH + tile * 128 + m0) * D + fb;
            s1 = s0 + D;
        } else if (mode == 2) {
            int g0 = tile * 128 + m0;
            int p0 = g0 & 31, bp0 = g0 >> 5;          // n_out = 32
            int tree = bp0 >> 10, b = bp0 & 1023;
            int leaf0 = 2 * p0 + half;                // p0 even -> p0+1 same (b,tree)
            const int* tbl = tree ? right : left;
            int v0 = __ldg(tbl + b * 64 + leaf0);
            int v1 = __ldg(tbl + b * 64 + leaf0 + 2);
            s0 = g_vocT + (size_t)v0 * D + fb;
            s1 = g_vocT + (size_t)v1 * D + fb;
        } else {
            int g0 = tile * 128 + m0, g1 = g0 + 1;
            int p0 = g0 % n_out, bp0 = g0 / n_out;
            int p1 = g1 % n_out, bp1 = g1 / n_out;
            s0 = Xin + (size_t)(bp0 * 2 * n_out + 2 * p0 + half) * D + fb;
            s1 = Xin + (size_t)(bp1 * 2 * n_out + 2 * p1 + half) * D + fb;
        }
#pragma unroll
        for (int j4 = 0; j4 < 32; j4 += 4) {
            float4 v0 = *(const float4*)(s0 + j4);
            float4 v1 = *(const float4*)(s1 + j4);
            if (mode == 2) {
                float4 bb = *(const float4*)(voc_b + fb + j4);
                v0.x += bb.x; v0.y += bb.y; v0.z += bb.z; v0.w += bb.w;
                v1.x += bb.x; v1.y += bb.y; v1.z += bb.z; v1.w += bb.w;
            }
            int fg = (half * 64 + fb + j4) * 64 + mp;
            Tw[fg]       = pack_bf16(v0.x, v1.x);
            Tw[fg + 64]  = pack_bf16(v0.y, v1.y);
            Tw[fg + 128] = pack_bf16(v0.z, v1.z);
            Tw[fg + 192] = pack_bf16(v0.w, v1.w);
        }
        if (t < 64) { Tw[128 * 64 + t] = 0x3F803F80u; Tw[129 * 64 + t] = 0u; }
    }

    const int l = t & 31, wid = t >> 5;
    const int qr = l >> 2, qc = l & 3;
    const int m0 = (wid & 3) * 32;
    const int n0 = (wid >> 2) * 32;
    const int mloc = t & 127;
    const int kh2 = (t >> 7) * 8;
    const char* Tm = (const char*)Tw + mloc * 2;

    float acc[2][4][4] = {};

#define AGEN(c)                                                                      \
    do {                                                                             \
        const int4* ix = (const int4*)(smem + SO_IDX + ((c) % 3) * 256) + kh2;       \
        uint32_t* Ad = As + ((c) & 1) * (16 * AP) + mloc;                            \
        _Pragma("unroll")                                                            \
        for (int q = 0; q < 8; q++) {                                                \
            int4 p = ix[q];                                                          \
            unsigned short a0 = *(const unsigned short*)(Tm + p.x);                  \
            unsigned short b0 = *(const unsigned short*)(Tm + p.y);                  \
            unsigned short a1 = *(const unsigned short*)(Tm + p.z);                  \
            unsigned short b1 = *(const unsigned short*)(Tm + p.w);                  \
            uint32_t av, bv, w;                                                      \
            asm("mov.b32 %0, {%1,%2};" : "=r"(av) : "h"(a0), "h"(a1));               \
            asm("mov.b32 %0, {%1,%2};" : "=r"(bv) : "h"(b0), "h"(b1));               \
            asm("mul.rn.bf16x2 %0, %1, %2;" : "=r"(w) : "r"(av), "r"(bv));           \
            Ad[(kh2 + q) * AP] = w;                                                  \
        }                                                                            \
    } while (0)

    CPWAIT(1);
    __syncthreads();
    AGEN(c0);

    for (int c = c0; c < c1; c++) {
        CPWAIT(0);
        __syncthreads();    // A(c) + W(c) visible; prior MMA reads complete
        if (c + 2 < c1) STAGE(c + 2);
        if (c + 1 < c1) AGEN(c + 1);

        const uint32_t* Ab = As + (c & 1) * (16 * AP);
        const uint32_t* Wb = Ws + (c % 3) * 1152;
#pragma unroll
        for (int ks = 0; ks < 2; ks++) {
            const uint32_t* ap = Ab + (ks * 8 + qc) * AP;
            uint32_t af[2][4];
#pragma unroll
            for (int mf = 0; mf < 2; mf++) {
                int r = m0 + mf * 16 + qr;
                af[mf][0] = ap[r];
                af[mf][1] = ap[r + 8];
                af[mf][2] = ap[4 * AP + r];
                af[mf][3] = ap[4 * AP + r + 8];
            }
            const uint32_t* bp = Wb + (ks * 8 + qc) * WP + n0 + qr;
#pragma unroll
            for (int nf = 0; nf < 4; nf++) {
                uint32_t b0 = bp[nf * 8];
                uint32_t b1 = bp[4 * WP + nf * 8];
                mma16(acc[0][nf], af[0], b0, b1);
                mma16(acc[1][nf], af[1], b0, b1);
            }
        }
    }

    // ---- epilogue ----
#pragma unroll
    for (int mf = 0; mf < 2; mf++) {
#pragma unroll
        for (int nf = 0; nf < 4; nf++) {
            int row = m0 + mf * 16 + qr;
            int col = n0 + nf * 8 + qc * 2;
            float* a4 = acc[mf][nf];
            if (split == 1) {
                float b0v = __ldg(bias + col), b1v = __ldg(bias + col + 1);
                float* dst = Xout + (size_t)(tile * 128 + row) * D + col;
                *(float2*)dst = make_float2(tanhf(a4[0] + b0v), tanhf(a4[1] + b1v));
                dst += 8 * D;
                *(float2*)dst = make_float2(tanhf(a4[2] + b0v), tanhf(a4[3] + b1v));
            } else {
                float* dst = part + (size_t)(s * ntiles + tile) * 8192 + row * 64 + col;
                *(float2*)dst = make_float2(a4[0], a4[1]);
                *(float2*)(dst + 8 * 64) = make_float2(a4[2], a4[3]);
            }
        }
    }
#undef STAGE
#undef AGEN
}

// -------- sum K-split partials + bias + tanh --------
__global__ void __launch_bounds__(256) k_reduce(const float* __restrict__ part,
                                                float* __restrict__ Xout,
                                                const float* __restrict__ bias,
                                                int ntiles, int split) {
    int tile = blockIdx.x;
    for (int idx = threadIdx.x; idx < 8192; idx += 256) {
        float sum = 0.f;
        for (int s = 0; s < split; s++) sum += part[(size_t)(s * ntiles + tile) * 8192 + idx];
        Xout[(size_t)tile * 8192 + idx] = tanhf(sum + bias[idx & 63]);
    }
}

// -------- final epilogue: reduce + bias + leaky + logits + softmax --------
__global__ void __launch_bounds__(256) k_final_reduce(const float* __restrict__ part,
                                                      float* __restrict__ out,
                                                      const float* __restrict__ bias,
                                                      const float* __restrict__ sm_w,
                                                      const float* __restrict__ sm_b,
                                                      int split) {
    __shared__ float actT[64 * 132];
    const int tile = blockIdx.x;
    const int t = threadIdx.x;
    const int ntiles = BATCH / 128;

    for (int idx = t; idx < 8192; idx += 256) {
        float sum = 0.f;
        for (int s = 0; s < split; s++) sum += part[(size_t)(s * ntiles + tile) * 8192 + idx];
        sum += bias[idx & 63];
        sum = (sum > 0.f) ? sum : 0.01f * sum;
        actT[(idx & 63) * 132 + (idx >> 6)] = sum;
    }
    __syncthreads();

    if (t < 128) {
        int m = t;
        float lg[NREL];
#pragma unroll
        for (int c = 0; c < NREL; c++) {
            float ssum = sm_b[c];
#pragma unroll 8
            for (int e = 0; e < 64; e++) ssum += actT[e * 132 + m] * sm_w[c * 64 + e];
            lg[c] = ssum;
        }
        float mx = lg[0];
#pragma unroll
        for (int c = 1; c < NREL; c++) mx = fmaxf(mx, lg[c]);
        float sum = 0.f;
#pragma unroll
        for (int c = 0; c < NREL; c++) { lg[c] = expf(lg[c] - mx); sum += lg[c]; }
        float inv = 1.f / sum;
#pragma unroll
        for (int c = 0; c < NREL; c++) out[(tile * 128 + m) * NREL + c] = lg[c] * inv;
    }
}

// -------- launcher --------
extern "C" void kernel_launch(void* const* d_in, const int* in_sizes, int n_in,
                              void* d_out, int out_size) {
    (void)in_sizes; (void)n_in; (void)out_size;
    const int*   left   = (const int*)d_in[0];
    const int*   right  = (const int*)d_in[1];
    const float* voc_w  = (const float*)d_in[2];
    const float* voc_b  = (const float*)d_in[3];
    const float* cps_w  = (const float*)d_in[4];
    const float* cps_b  = (const float*)d_in[5];
    const float* cpst_w = (const float*)d_in[6];
    const float* cpst_b = (const float*)d_in[7];
    const float* cpr_w  = (const float*)d_in[8];
    const float* cpr_b  = (const float*)d_in[9];
    const float* cprt_w = (const float*)d_in[10];
    const float* cprt_b = (const float*)d_in[11];
    const float* sm_w   = (const float*)d_in[12];
    const float* sm_b   = (const float*)d_in[13];
    float* out = (float*)d_out;

    float *XA, *XB, *bc, *bf, *part;
    uint32_t *Wc2, *Wf2;
    int *idxC, *idxF;
    cudaGetSymbolAddress((void**)&XA, g_XA);
    cudaGetSymbolAddress((void**)&XB, g_XB);
    cudaGetSymbolAddress((void**)&Wc2, g_Wc2);
    cudaGetSymbolAddress((void**)&Wf2, g_Wf2);
    cudaGetSymbolAddress((void**)&bc, g_bc);
    cudaGetSymbolAddress((void**)&bf, g_bf);
    cudaGetSymbolAddress((void**)&part, g_part);
    cudaGetSymbolAddress((void**)&idxC, g_idxC);
    cudaGetSymbolAddress((void**)&idxF, g_idxF);

    cudaFuncSetAttribute(k_gemm, cudaFuncAttributeMaxDynamicSharedMemorySize, SMEM_BYTES);

    k_transpose_voc<<<(VOC + 63) / 64, 256>>>(voc_w);
    k_prep<<<NCHC + NCHF + 3, 256>>>(cps_w, cps_b, cpst_w, cpst_b,
                                     cpr_w, cpr_b, cprt_w, cprt_b);

    // level 1 (fused vocab gather): 512 tiles, split 1
    k_gemm<<<512, 256, SMEM_BYTES>>>(nullptr, XB, part, Wc2, idxC, bc,
                                     left, right, voc_b, 32, NCHC, 1, 512, 2);
    // level 2: 256 tiles, split 2 (512 blocks)
    k_gemm<<<512, 256, SMEM_BYTES>>>(XB, XA, part, Wc2, idxC, bc,
                                     left, right, voc_b, 16, NCHC, 2, 256, 0);
    k_reduce<<<256, 256>>>(part, XA, bc, 256, 2);
    // level 3: 128 tiles, split 2 (256 blocks)
    k_gemm<<<256, 256, SMEM_BYTES>>>(XA, XB, part, Wc2, idxC, bc,
                                     left, right, voc_b, 8, NCHC, 2, 128, 0);
    k_reduce<<<128, 256>>>(part, XB, bc, 128, 2);
    // level 4: 64 tiles, split 5 (320 blocks)
    k_gemm<<<320, 256, SMEM_BYTES>>>(XB, XA, part, Wc2, idxC, bc,
                                     left, right, voc_b, 4, NCHC, 5, 64, 0);
    k_reduce<<<64, 256>>>(part, XA, bc, 64, 5);
    // level 5: 32 tiles, split 10 (320 blocks)
    k_gemm<<<320, 256, SMEM_BYTES>>>(XA, XB, part, Wc2, idxC, bc,
                                     left, right, voc_b, 2, NCHC, 10, 32, 0);
    k_reduce<<<32, 256>>>(part, XB, bc, 32, 10);
    // level 6: 16 tiles, split 14 (224 blocks)
    k_gemm<<<224, 256, SMEM_BYTES>>>(XB, XA, part, Wc2, idxC, bc,
                                     left, right, voc_b, 1, NCHC, 14, 16, 0);
    k_reduce<<<16, 256>>>(part, XA, bc, 16, 14);
    // final: 8 tiles, split 33 (264 blocks)
    k_gemm<<<264, 256, SMEM_BYTES>>>(XA, XB, part, Wf2, idxF, bf,
                                     left, right, voc_b, 1, NCHF, 33, 8, 1);
    k_final_reduce<<<BATCH / 128, 256>>>(part, out, bf, sm_w, sm_b, 33);
}

// round 9
// speedup vs baseline: 1.3802x; 1.0380x over previous
#include <cuda_runtime.h>
#include <cuda_bf16.h>
#include <math.h>
#include <cstdint>

#define BATCH 1024
#define D     64
#define VOC   50000
#define NREL  7
#define KC    2240      // folded compose K: 2080 tri + 128 linear + 32 pad
#define NCHC  70
#define KF    4224      // final K: 4096 kron + 128 linear
#define NCHF  132

// smem byte layout (total 64 KB -> 3 CTAs/SM)
#define SO_IDX 0           // 3 x 256 B idx slots
#define SO_T   1024        // T bf16 [130 f][128 m] = 33280 B
#define SO_A   34304       // 2 x (16 k2 x 136) words = 17408 B
#define SO_W   51712       // 3 x (16 k2 x 72) words = 13824 B
#define SMEM_BYTES 65536
#define AP 136             // A pitch (words per k2 row)
#define WP 72              // W pitch

// -------- device scratch --------
__device__ float    g_vocT[VOC * D];
__device__ float    g_XB[2 * BATCH * 32 * D];   // level-1 output
__device__ uint32_t g_Wc2[NCHC * 1024];   // bf16x2 compose W chunks [c][k2*64+e]
__device__ uint32_t g_Wf2[NCHF * 1024];   // bf16x2 final W chunks
__device__ int      g_idxC[KC * 2];       // per k: (a_off, b_off) byte offsets into T
__device__ int      g_idxF[KF * 2];
__device__ float    g_bc[D];
__device__ float    g_bf[D];
__device__ float    g_partA[512 * 8192];  // K-split partials ping (16.8 MB)
__device__ float    g_partB[320 * 8192];  // K-split partials pong (10.5 MB)

// -------- PTX helpers --------
__device__ __forceinline__ uint32_t s2u(const void* p) {
    uint32_t a;
    asm("{.reg .u64 t; cvta.to.shared.u64 t, %1; cvt.u32.u64 %0, t;}" : "=r"(a) : "l"(p));
    return a;
}
__device__ __forceinline__ void mma16(float* d, const uint32_t* a, uint32_t b0, uint32_t b1) {
    asm volatile(
        "mma.sync.aligned.m16n8k16.row.col.f32.bf16.bf16.f32 "
        "{%0,%1,%2,%3},{%4,%5,%6,%7},{%8,%9},{%0,%1,%2,%3};"
        : "+f"(d[0]), "+f"(d[1]), "+f"(d[2]), "+f"(d[3])
        : "r"(a[0]), "r"(a[1]), "r"(a[2]), "r"(a[3]), "r"(b0), "r"(b1));
}
__device__ __forceinline__ uint32_t pack_bf16(float lo, float hi) {
    uint32_t d;
    asm("cvt.rn.bf16x2.f32 %0, %1, %2;" : "=r"(d) : "f"(hi), "f"(lo));
    return d;
}
#define CPA16(dst, src) \
    asm volatile("cp.async.ca.shared.global [%0], [%1], 16;" :: "r"(dst), "l"(src))
#define CPCOMMIT() asm volatile("cp.async.commit_group;")
#define CPWAIT(n)  asm volatile("cp.async.wait_group %0;" :: "n"(n) : "memory")

// -------- vocab transpose: (64, 50000) -> (50000, 64) --------
__global__ void k_transpose_voc(const float* __restrict__ voc_w) {
    __shared__ float tile[64][65];
    int v0 = blockIdx.x * 64;
    for (int idx = threadIdx.x; idx < 64 * 64; idx += 256) {
        int d = idx >> 6, vv = idx & 63;
        int v = v0 + vv;
        tile[vv][d] = (v < VOC) ? voc_w[d * VOC + v] : 0.f;
    }
    __syncthreads();
    for (int idx = threadIdx.x; idx < 64 * 64; idx += 256) {
        int vv = idx >> 6, d = idx & 63;
        int v = v0 + vv;
        if (v < VOC) g_vocT[v * D + d] = tile[vv][d];
    }
}

// -------- weight/index prep --------
__device__ __forceinline__ int tri_i_of_k(int k) {
    int i = (int)floorf((sqrtf(8.f * (float)k + 1.f) - 1.f) * 0.5f);
    while ((i + 1) * (i + 2) / 2 <= k) i++;
    while (i * (i + 1) / 2 > k) i--;
    return i;
}
__device__ __forceinline__ float foldc(const float* cpst_w, const float* cps_w, int k, int e) {
    if (k < 2080) {
        int i = tri_i_of_k(k);
        int j = k - i * (i + 1) / 2;
        return (j < i) ? cpst_w[e * 4096 + i * 64 + j] + cpst_w[e * 4096 + j * 64 + i]
                       : cpst_w[e * 4096 + i * 65];
    } else if (k < 2208) {
        return cps_w[e * 128 + (k - 2080)];
    }
    return 0.f;
}
__global__ void k_prep(const float* __restrict__ cps_w,  const float* __restrict__ cps_b,
                       const float* __restrict__ cpst_w, const float* __restrict__ cpst_b,
                       const float* __restrict__ cpr_w,  const float* __restrict__ cpr_b,
                       const float* __restrict__ cprt_w, const float* __restrict__ cprt_b) {
    int blk = blockIdx.x, t = threadIdx.x;
    if (blk < NCHC) {
        int c = blk;
        for (int u = t; u < 1024; u += 256) {
            int e = u & 63, k2 = u >> 6;
            int k = c * 32 + 2 * k2;
            float v0 = foldc(cpst_w, cps_w, k, e);
            float v1 = foldc(cpst_w, cps_w, k + 1, e);
            g_Wc2[c * 1024 + u] = pack_bf16(v0, v1);
        }
    } else if (blk < NCHC + NCHF) {
        int c = blk - NCHC;
        for (int u = t; u < 1024; u += 256) {
            int e = u & 63, k2 = u >> 6;
            int k = c * 32 + 2 * k2;
            float v0 = (k < 4096) ? cprt_w[e * 4096 + k] : cpr_w[e * 128 + (k - 4096)];
            float v1 = (k + 1 < 4096) ? cprt_w[e * 4096 + k + 1] : cpr_w[e * 128 + (k + 1 - 4096)];
            g_Wf2[c * 1024 + u] = pack_bf16(v0, v1);
        }
    } else if (blk == NCHC + NCHF) {
        if (t < D) {
            g_bc[t] = cps_b[t] + cpst_b[t];
            g_bf[t] = cpr_b[t] + cprt_b[t];
        }
    } else if (blk == NCHC + NCHF + 1) {
        for (int k = t; k < KC; k += 256) {
            int a, b2;
            if (k < 2080) { int i = tri_i_of_k(k); a = i; b2 = k - i * (i + 1) / 2; }
            else if (k < 2208) { a = k - 2080; b2 = 128; }
            else { a = 129; b2 = 129; }
            g_idxC[k * 2] = a * 256;
            g_idxC[k * 2 + 1] = b2 * 256;
        }
    } else {
        for (int k = t; k < KF; k += 256) {
            int a, b2;
            if (k < 4096) { a = k >> 6; b2 = 64 + (k & 63); }
            else { a = k - 4096; b2 = 128; }
            g_idxF[k * 2] = a * 256;
            g_idxF[k * 2 + 1] = b2 * 256;
        }
    }
}

// -------- pipelined bf16 tensor GEMM level (fused split-K input reduction) --------
// mode: 0 compose, 1 final, 2 level1 (fused vocab gather)
__global__ void __launch_bounds__(256, 3) k_gemm(const float* __restrict__ Xin,
                                                 float* __restrict__ Xout,
                                                 const float* __restrict__ inpart,
                                                 float* __restrict__ outpart,
                                                 const uint32_t* __restrict__ Wq,
                                                 const int* __restrict__ idx,
                                                 const float* __restrict__ t_bias,
                                                 const float* __restrict__ e_bias,
                                                 const int* __restrict__ left,
                                                 const int* __restrict__ right,
                                                 const float* __restrict__ voc_b,
                                                 int n_out, int nchunks, int split,
                                                 int ntiles, int prev_split, int prev_ntiles,
                                                 int mode) {
    extern __shared__ char smem[];
    const uint32_t sbase = s2u(smem);
    uint32_t* Tw = (uint32_t*)(smem + SO_T);      // bf16 pairs: word f*64 + m/2
    uint32_t* As = (uint32_t*)(smem + SO_A);
    uint32_t* Ws = (uint32_t*)(smem + SO_W);
    const int t = threadIdx.x;
    const int s = blockIdx.x % split;
    const int tile = blockIdx.x / split;
    const int cpb = nchunks / split;     // NOTE: all chosen splits give cpb >= 2
    const int c0 = s * cpb, c1 = c0 + cpb;

#define STAGE(c)                                                                     \
    do {                                                                             \
        int _slot = (c) % 3;                                                         \
        uint32_t _wd = sbase + SO_W +                                                \
            (uint32_t)(_slot * 1152 + (t >> 4) * WP + (t & 15) * 4) * 4;             \
        CPA16(_wd, Wq + (size_t)(c) * 1024 + t * 4);                                 \
        if (t < 16)                                                                  \
            CPA16(sbase + SO_IDX + _slot * 256 + t * 16, idx + (c) * 64 + t * 4);    \
        CPCOMMIT();                                                                  \
    } while (0)

    STAGE(c0);
    STAGE(c0 + 1);   // cpb >= 2 always

    // ---- load/reduce L/R into T (bf16, m-pairs packed) + ones/zeros rows ----
    {
        int mp = t & 63, half = (t >> 6) & 1, fb = (t >> 7) * 32;
        int m0 = 2 * mp;
        if (mode == 2) {
            int g0 = tile * 128 + m0;
            int p0 = g0 & 31, bp0 = g0 >> 5;          // n_out = 32
            int tree = bp0 >> 10, b = bp0 & 1023;
            int leaf0 = 2 * p0 + half;
            const int* tbl = tree ? right : left;
            int v0i = __ldg(tbl + b * 64 + leaf0);
            int v1i = __ldg(tbl + b * 64 + leaf0 + 2);
            const float* s0 = g_vocT + (size_t)v0i * D + fb;
            const float* s1 = g_vocT + (size_t)v1i * D + fb;
#pragma unroll
            for (int j4 = 0; j4 < 32; j4 += 4) {
                float4 v0 = *(const float4*)(s0 + j4);
                float4 v1 = *(const float4*)(s1 + j4);
                float4 bb = *(const float4*)(voc_b + fb + j4);
                v0.x += bb.x; v0.y += bb.y; v0.z += bb.z; v0.w += bb.w;
                v1.x += bb.x; v1.y += bb.y; v1.z += bb.z; v1.w += bb.w;
                int fg = (half * 64 + fb + j4) * 64 + mp;
                Tw[fg]       = pack_bf16(v0.x, v1.x);
                Tw[fg + 64]  = pack_bf16(v0.y, v1.y);
                Tw[fg + 128] = pack_bf16(v0.z, v1.z);
                Tw[fg + 192] = pack_bf16(v0.w, v1.w);
            }
        } else {
            int ga, gb;
            if (mode == 1) {
                ga = half * BATCH + tile * 128 + m0;
                gb = ga + 1;
            } else {
                int g0 = tile * 128 + m0, g1 = g0 + 1;
                int p0 = g0 % n_out, bp0 = g0 / n_out;
                int p1 = g1 % n_out, bp1 = g1 / n_out;
                ga = bp0 * 2 * n_out + 2 * p0 + half;
                gb = bp1 * 2 * n_out + 2 * p1 + half;
            }
            if (prev_split == 1) {
                const float* s0 = Xin + (size_t)ga * D + fb;
                const float* s1 = Xin + (size_t)gb * D + fb;
#pragma unroll
                for (int j4 = 0; j4 < 32; j4 += 4) {
                    float4 v0 = *(const float4*)(s0 + j4);
                    float4 v1 = *(const float4*)(s1 + j4);
                    int fg = (half * 64 + fb + j4) * 64 + mp;
                    Tw[fg]       = pack_bf16(v0.x, v1.x);
                    Tw[fg + 64]  = pack_bf16(v0.y, v1.y);
                    Tw[fg + 128] = pack_bf16(v0.z, v1.z);
                    Tw[fg + 192] = pack_bf16(v0.w, v1.w);
                }
            } else {
                // fused split-K reduction of previous level + bias + tanh
                size_t stride = (size_t)prev_ntiles * 8192;
                const float* b0 = inpart + (size_t)(ga >> 7) * 8192 + (ga & 127) * 64 + fb;
                const float* b1 = inpart + (size_t)(gb >> 7) * 8192 + (gb & 127) * 64 + fb;
#pragma unroll
                for (int j4 = 0; j4 < 32; j4 += 4) {
                    float4 v0 = *(const float4*)(b0 + j4);
                    float4 v1 = *(const float4*)(b1 + j4);
                    int sp = 1;
                    for (; sp + 1 < prev_split; sp += 2) {
                        float4 u0 = *(const float4*)(b0 + sp * stride + j4);
                        float4 u1 = *(const float4*)(b1 + sp * stride + j4);
                        float4 w0 = *(const float4*)(b0 + (sp + 1) * stride + j4);
                        float4 w1 = *(const float4*)(b1 + (sp + 1) * stride + j4);
                        v0.x += u0.x + w0.x; v0.y += u0.y + w0.y;
                        v0.z += u0.z + w0.z; v0.w += u0.w + w0.w;
                        v1.x += u1.x + w1.x; v1.y += u1.y + w1.y;
                        v1.z += u1.z + w1.z; v1.w += u1.w + w1.w;
                    }
                    if (sp < prev_split) {
                        float4 u0 = *(const float4*)(b0 + sp * stride + j4);
                        float4 u1 = *(const float4*)(b1 + sp * stride + j4);
                        v0.x += u0.x; v0.y += u0.y; v0.z += u0.z; v0.w += u0.w;
                        v1.x += u1.x; v1.y += u1.y; v1.z += u1.z; v1.w += u1.w;
                    }
                    float4 bb = *(const float4*)(t_bias + fb + j4);
                    v0.x = tanhf(v0.x + bb.x); v0.y = tanhf(v0.y + bb.y);
                    v0.z = tanhf(v0.z + bb.z); v0.w = tanhf(v0.w + bb.w);
                    v1.x = tanhf(v1.x + bb.x); v1.y = tanhf(v1.y + bb.y);
                    v1.z = tanhf(v1.z + bb.z); v1.w = tanhf(v1.w + bb.w);
                    int fg = (half * 64 + fb + j4) * 64 + mp;
                    Tw[fg]       = pack_bf16(v0.x, v1.x);
                    Tw[fg + 64]  = pack_bf16(v0.y, v1.y);
                    Tw[fg + 128] = pack_bf16(v0.z, v1.z);
                    Tw[fg + 192] = pack_bf16(v0.w, v1.w);
                }
            }
        }
        if (t < 64) { Tw[128 * 64 + t] = 0x3F803F80u; Tw[129 * 64 + t] = 0u; }
    }

    const int l = t & 31, wid = t >> 5;
    const int qr = l >> 2, qc = l & 3;
    const int m0 = (wid & 3) * 32;
    const int n0 = (wid >> 2) * 32;
    const int mloc = t & 127;
    const int kh2 = (t >> 7) * 8;
    const char* Tm = (const char*)Tw + mloc * 2;

    float acc[2][4][4] = {};

#define AGEN(c)                                                                      \
    do {                                                                             \
        const int4* ix = (const int4*)(smem + SO_IDX + ((c) % 3) * 256) + kh2;       \
        uint32_t* Ad = As + ((c) & 1) * (16 * AP) + mloc;                            \
        _Pragma("unroll")                                                            \
        for (int q = 0; q < 8; q++) {                                                \
            int4 p = ix[q];                                                          \
            unsigned short a0 = *(const unsigned short*)(Tm + p.x);                  \
            unsigned short b0 = *(const unsigned short*)(Tm + p.y);                  \
            unsigned short a1 = *(const unsigned short*)(Tm + p.z);                  \
            unsigned short b1 = *(const unsigned short*)(Tm + p.w);                  \
            uint32_t av, bv, w;                                                      \
            asm("mov.b32 %0, {%1,%2};" : "=r"(av) : "h"(a0), "h"(a1));               \
            asm("mov.b32 %0, {%1,%2};" : "=r"(bv) : "h"(b0), "h"(b1));               \
            asm("mul.rn.bf16x2 %0, %1, %2;" : "=r"(w) : "r"(av), "r"(bv));           \
            Ad[(kh2 + q) * AP] = w;                                                  \
        }                                                                            \
    } while (0)

    // first A tile: need idx(c0) -> both initial groups must land
    CPWAIT(1);            // group c0 complete
    __syncthreads();
    AGEN(c0);

    for (int c = c0; c < c1; c++) {
        // group c already drained (pre-loop wait for c0; inner wait of iter c-1 for c>c0)
        __syncthreads();  // A(c) visible to all warps; prior MMA reads of W slot done
        if (c + 2 < c1) {
            STAGE(c + 2);
            CPWAIT(1);    // group c+1 complete; c+2 in flight for a full chunk body
        } else {
            CPWAIT(0);    // tail: drain everything
        }
        if (c + 1 < c1) AGEN(c + 1);

        const uint32_t* Ab = As + (c & 1) * (16 * AP);
        const uint32_t* Wb = Ws + (c % 3) * 1152;
#pragma unroll
        for (int ks = 0; ks < 2; ks++) {
            const uint32_t* ap = Ab + (ks * 8 + qc) * AP;
            uint32_t af[2][4];
#pragma unroll
            for (int mf = 0; mf < 2; mf++) {
                int r = m0 + mf * 16 + qr;
                af[mf][0] = ap[r];
                af[mf][1] = ap[r + 8];
                af[mf][2] = ap[4 * AP + r];
                af[mf][3] = ap[4 * AP + r + 8];
            }
            const uint32_t* bp = Wb + (ks * 8 + qc) * WP + n0 + qr;
#pragma unroll
            for (int nf = 0; nf < 4; nf++) {
                uint32_t b0 = bp[nf * 8];
                uint32_t b1 = bp[4 * WP + nf * 8];
                mma16(acc[0][nf], af[0], b0, b1);
                mma16(acc[1][nf], af[1], b0, b1);
            }
        }
    }

    // ---- epilogue ----
#pragma unroll
    for (int mf = 0; mf < 2; mf++) {
#pragma unroll
        for (int nf = 0; nf < 4; nf++) {
            int row = m0 + mf * 16 + qr;
            int col = n0 + nf * 8 + qc * 2;
            float* a4 = acc[mf][nf];
            if (split == 1) {
                float b0v = __ldg(e_bias + col), b1v = __ldg(e_bias + col + 1);
                float* dst = Xout + (size_t)(tile * 128 + row) * D + col;
                *(float2*)dst = make_float2(tanhf(a4[0] + b0v), tanhf(a4[1] + b1v));
                dst += 8 * D;
                *(float2*)dst = make_float2(tanhf(a4[2] + b0v), tanhf(a4[3] + b1v));
            } else {
                float* dst = outpart + (size_t)(s * ntiles + tile) * 8192 + row * 64 + col;
                *(float2*)dst = make_float2(a4[0], a4[1]);
                *(float2*)(dst + 8 * 64) = make_float2(a4[2], a4[3]);
            }
        }
    }
#undef STAGE
#undef AGEN
}

// -------- final epilogue: reduce + bias + leaky + logits + softmax --------
__global__ void __launch_bounds__(256) k_final_reduce(const float* __restrict__ part,
                                                      float* __restrict__ out,
                                                      const float* __restrict__ bias,
                                                      const float* __restrict__ sm_w,
                                                      const float* __restrict__ sm_b,
                                                      int split) {
    __shared__ float actT[64 * 132];
    const int tile = blockIdx.x;
    const int t = threadIdx.x;
    const int ntiles = BATCH / 128;

    for (int idx = t; idx < 8192; idx += 256) {
        float sum = 0.f;
        for (int s = 0; s < split; s++) sum += part[(size_t)(s * ntiles + tile) * 8192 + idx];
        sum += bias[idx & 63];
        sum = (sum > 0.f) ? sum : 0.01f * sum;
        actT[(idx & 63) * 132 + (idx >> 6)] = sum;
    }
    __syncthreads();

    if (t < 128) {
        int m = t;
        float lg[NREL];
#pragma unroll
        for (int c = 0; c < NREL; c++) {
            float ssum = sm_b[c];
#pragma unroll 8
            for (int e = 0; e < 64; e++) ssum += actT[e * 132 + m] * sm_w[c * 64 + e];
            lg[c] = ssum;
        }
        float mx = lg[0];
#pragma unroll
        for (int c = 1; c < NREL; c++) mx = fmaxf(mx, lg[c]);
        float sum = 0.f;
#pragma unroll
        for (int c = 0; c < NREL; c++) { lg[c] = expf(lg[c] - mx); sum += lg[c]; }
        float inv = 1.f / sum;
#pragma unroll
        for (int c = 0; c < NREL; c++) out[(tile * 128 + m) * NREL + c] = lg[c] * inv;
    }
}

// -------- launcher --------
extern "C" void kernel_launch(void* const* d_in, const int* in_sizes, int n_in,
                              void* d_out, int out_size) {
    (void)in_sizes; (void)n_in; (void)out_size;
    const int*   left   = (const int*)d_in[0];
    const int*   right  = (const int*)d_in[1];
    const float* voc_w  = (const float*)d_in[2];
    const float* voc_b  = (const float*)d_in[3];
    const float* cps_w  = (const float*)d_in[4];
    const float* cps_b  = (const float*)d_in[5];
    const float* cpst_w = (const float*)d_in[6];
    const float* cpst_b = (const float*)d_in[7];
    const float* cpr_w  = (const float*)d_in[8];
    const float* cpr_b  = (const float*)d_in[9];
    const float* cprt_w = (const float*)d_in[10];
    const float* cprt_b = (const float*)d_in[11];
    const float* sm_w   = (const float*)d_in[12];
    const float* sm_b   = (const float*)d_in[13];
    float* out = (float*)d_out;

    float *XB, *bc, *bf, *pA, *pB;
    uint32_t *Wc2, *Wf2;
    int *idxC, *idxF;
    cudaGetSymbolAddress((void**)&XB, g_XB);
    cudaGetSymbolAddress((void**)&Wc2, g_Wc2);
    cudaGetSymbolAddress((void**)&Wf2, g_Wf2);
    cudaGetSymbolAddress((void**)&bc, g_bc);
    cudaGetSymbolAddress((void**)&bf, g_bf);
    cudaGetSymbolAddress((void**)&pA, g_partA);
    cudaGetSymbolAddress((void**)&pB, g_partB);
    cudaGetSymbolAddress((void**)&idxC, g_idxC);
    cudaGetSymbolAddress((void**)&idxF, g_idxF);

    cudaFuncSetAttribute(k_gemm, cudaFuncAttributeMaxDynamicSharedMemorySize, SMEM_BYTES);

    k_transpose_voc<<<(VOC + 63) / 64, 256>>>(voc_w);
    k_prep<<<NCHC + NCHF + 3, 256>>>(cps_w, cps_b, cpst_w, cpst_b,
                                     cpr_w, cpr_b, cprt_w, cprt_b);

    // L1 (vocab gather): 512 tiles, split 1 -> XB (tanh applied)
    k_gemm<<<512, 256, SMEM_BYTES>>>(nullptr, XB, nullptr, nullptr, Wc2, idxC, bc, bc,
                                     left, right, voc_b, 32, NCHC, 1, 512, 1, 0, 2);
    // L2: 256 tiles, split 2 -> partA (512 slots)
    k_gemm<<<512, 256, SMEM_BYTES>>>(XB, nullptr, nullptr, pA, Wc2, idxC, bc, bc,
                                     left, right, voc_b, 16, NCHC, 2, 256, 1, 0, 0);
    // L3: 128 tiles, split 2; reads partA (prev 2 x 256) -> partB (256 slots)
    k_gemm<<<256, 256, SMEM_BYTES>>>(nullptr, nullptr, pA, pB, Wc2, idxC, bc, bc,
                                     left, right, voc_b, 8, NCHC, 2, 128, 2, 256, 0);
    // L4: 64 tiles, split 5; reads partB (2 x 128) -> partA (320 slots)
    k_gemm<<<320, 256, SMEM_BYTES>>>(nullptr, nullptr, pB, pA, Wc2, idxC, bc, bc,
                                     left, right, voc_b, 4, NCHC, 5, 64, 2, 128, 0);
    // L5: 32 tiles, split 10; reads partA (5 x 64) -> partB (320 slots)
    k_gemm<<<320, 256, SMEM_BYTES>>>(nullptr, nullptr, pA, pB, Wc2, idxC, bc, bc,
                                     left, right, voc_b, 2, NCHC, 10, 32, 5, 64, 0);
    // L6: 16 tiles, split 14; reads partB (10 x 32) -> partA (224 slots)
    k_gemm<<<224, 256, SMEM_BYTES>>>(nullptr, nullptr, pB, pA, Wc2, idxC, bc, bc,
                                     left, right, voc_b, 1, NCHC, 14, 16, 10, 32, 0);
    // final: 8 tiles, split 33; reads partA (14 x 16) -> partB (264 slots)
    k_gemm<<<264, 256, SMEM_BYTES>>>(nullptr, nullptr, pA, pB, Wf2, idxF, bc, bf,
                                     left, right, voc_b, 1, NCHF, 33, 8, 14, 16, 1);
    k_final_reduce<<<BATCH / 128, 256>>>(pB, out, bf, sm_w, sm_b, 33);
}

// round 10
// speedup vs baseline: 1.6201x; 1.1738x over previous
#include <cuda_runtime.h>
#include <cuda_bf16.h>
#include <math.h>
#include <cstdint>

#define BATCH 1024
#define D     64
#define VOC   50000
#define NREL  7
#define KC    2240      // folded compose K: 2080 tri + 128 linear + 32 pad
#define NCHC  70
#define KF    4224      // final K: 4096 kron + 128 linear
#define NCHF  132

// smem byte layout (total 64 KB -> 3 CTAs/SM)
#define SO_IDX 0           // 3 x 256 B idx slots
#define SO_T   1024        // T bf16 [130 f][128 m] = 33280 B
#define SO_A   34304       // 2 x (16 k2 x 136) words = 17408 B
#define SO_W   51712       // 3 x (16 k2 x 72) words = 13824 B
#define SMEM_BYTES 65536
#define AP 136             // A pitch (words per k2 row)
#define WP 72              // W pitch

// -------- device scratch --------
__device__ float    g_vocT[VOC * D];
__device__ float    g_XA[2 * BATCH * 16 * D];   // reduced outputs (even levels)
__device__ float    g_XB[2 * BATCH * 32 * D];   // reduced outputs (odd levels)
__device__ uint32_t g_Wc2[NCHC * 1024];   // bf16x2 compose W chunks [c][k2*64+e]
__device__ uint32_t g_Wf2[NCHF * 1024];   // bf16x2 final W chunks
__device__ int      g_idxC[KC * 2];       // per k: (a_off, b_off) byte offsets into T
__device__ int      g_idxF[KF * 2];
__device__ float    g_bc[D];
__device__ float    g_bf[D];
__device__ float    g_partA[1024 * 8192]; // split partials ping (33.5 MB)
__device__ float    g_partB[1280 * 8192]; // split partials pong (41.9 MB)

// -------- PTX helpers --------
__device__ __forceinline__ uint32_t s2u(const void* p) {
    uint32_t a;
    asm("{.reg .u64 t; cvta.to.shared.u64 t, %1; cvt.u32.u64 %0, t;}" : "=r"(a) : "l"(p));
    return a;
}
__device__ __forceinline__ void mma16(float* d, const uint32_t* a, uint32_t b0, uint32_t b1) {
    asm volatile(
        "mma.sync.aligned.m16n8k16.row.col.f32.bf16.bf16.f32 "
        "{%0,%1,%2,%3},{%4,%5,%6,%7},{%8,%9},{%0,%1,%2,%3};"
        : "+f"(d[0]), "+f"(d[1]), "+f"(d[2]), "+f"(d[3])
        : "r"(a[0]), "r"(a[1]), "r"(a[2]), "r"(a[3]), "r"(b0), "r"(b1));
}
__device__ __forceinline__ uint32_t pack_bf16(float lo, float hi) {
    uint32_t d;
    asm("cvt.rn.bf16x2.f32 %0, %1, %2;" : "=r"(d) : "f"(hi), "f"(lo));
    return d;
}
#define CPA16(dst, src) \
    asm volatile("cp.async.ca.shared.global [%0], [%1], 16;" :: "r"(dst), "l"(src))
#define CPCOMMIT() asm volatile("cp.async.commit_group;")
#define CPWAIT(n)  asm volatile("cp.async.wait_group %0;" :: "n"(n) : "memory")

// -------- vocab transpose: (64, 50000) -> (50000, 64) --------
__global__ void k_transpose_voc(const float* __restrict__ voc_w) {
    __shared__ float tile[64][65];
    int v0 = blockIdx.x * 64;
    for (int idx = threadIdx.x; idx < 64 * 64; idx += 256) {
        int d = idx >> 6, vv = idx & 63;
        int v = v0 + vv;
        tile[vv][d] = (v < VOC) ? voc_w[d * VOC + v] : 0.f;
    }
    __syncthreads();
    for (int idx = threadIdx.x; idx < 64 * 64; idx += 256) {
        int vv = idx >> 6, d = idx & 63;
        int v = v0 + vv;
        if (v < VOC) g_vocT[v * D + d] = tile[vv][d];
    }
}

// -------- weight/index prep --------
__device__ __forceinline__ int tri_i_of_k(int k) {
    int i = (int)floorf((sqrtf(8.f * (float)k + 1.f) - 1.f) * 0.5f);
    while ((i + 1) * (i + 2) / 2 <= k) i++;
    while (i * (i + 1) / 2 > k) i--;
    return i;
}
__device__ __forceinline__ float foldc(const float* cpst_w, const float* cps_w, int k, int e) {
    if (k < 2080) {
        int i = tri_i_of_k(k);
        int j = k - i * (i + 1) / 2;
        return (j < i) ? cpst_w[e * 4096 + i * 64 + j] + cpst_w[e * 4096 + j * 64 + i]
                       : cpst_w[e * 4096 + i * 65];
    } else if (k < 2208) {
        return cps_w[e * 128 + (k - 2080)];
    }
    return 0.f;
}
__global__ void k_prep(const float* __restrict__ cps_w,  const float* __restrict__ cps_b,
                       const float* __restrict__ cpst_w, const float* __restrict__ cpst_b,
                       const float* __restrict__ cpr_w,  const float* __restrict__ cpr_b,
                       const float* __restrict__ cprt_w, const float* __restrict__ cprt_b) {
    int blk = blockIdx.x, t = threadIdx.x;
    if (blk < NCHC) {
        int c = blk;
        for (int u = t; u < 1024; u += 256) {
            int e = u & 63, k2 = u >> 6;
            int k = c * 32 + 2 * k2;
            float v0 = foldc(cpst_w, cps_w, k, e);
            float v1 = foldc(cpst_w, cps_w, k + 1, e);
            g_Wc2[c * 1024 + u] = pack_bf16(v0, v1);
        }
    } else if (blk < NCHC + NCHF) {
        int c = blk - NCHC;
        for (int u = t; u < 1024; u += 256) {
            int e = u & 63, k2 = u >> 6;
            int k = c * 32 + 2 * k2;
            float v0 = (k < 4096) ? cprt_w[e * 4096 + k] : cpr_w[e * 128 + (k - 4096)];
            float v1 = (k + 1 < 4096) ? cprt_w[e * 4096 + k + 1] : cpr_w[e * 128 + (k + 1 - 4096)];
            g_Wf2[c * 1024 + u] = pack_bf16(v0, v1);
        }
    } else if (blk == NCHC + NCHF) {
        if (t < D) {
            g_bc[t] = cps_b[t] + cpst_b[t];
            g_bf[t] = cpr_b[t] + cprt_b[t];
        }
    } else if (blk == NCHC + NCHF + 1) {
        for (int k = t; k < KC; k += 256) {
            int a, b2;
            if (k < 2080) { int i = tri_i_of_k(k); a = i; b2 = k - i * (i + 1) / 2; }
            else if (k < 2208) { a = k - 2080; b2 = 128; }
            else { a = 129; b2 = 129; }
            g_idxC[k * 2] = a * 256;
            g_idxC[k * 2 + 1] = b2 * 256;
        }
    } else {
        for (int k = t; k < KF; k += 256) {
            int a, b2;
            if (k < 4096) { a = k >> 6; b2 = 64 + (k & 63); }
            else { a = k - 4096; b2 = 128; }
            g_idxF[k * 2] = a * 256;
            g_idxF[k * 2 + 1] = b2 * 256;
        }
    }
}

// -------- pipelined bf16 tensor GEMM level --------
// mode: 0 compose, 1 final, 2 level1 (fused vocab gather)
__global__ void __launch_bounds__(256, 3) k_gemm(const float* __restrict__ Xin,
                                                 float* __restrict__ Xout,
                                                 float* __restrict__ outpart,
                                                 const uint32_t* __restrict__ Wq,
                                                 const int* __restrict__ idx,
                                                 const float* __restrict__ e_bias,
                                                 const int* __restrict__ left,
                                                 const int* __restrict__ right,
                                                 const float* __restrict__ voc_b,
                                                 int n_out, int nchunks, int split,
                                                 int ntiles, int mode) {
    extern __shared__ char smem[];
    const uint32_t sbase = s2u(smem);
    uint32_t* Tw = (uint32_t*)(smem + SO_T);      // bf16 pairs: word f*64 + m/2
    uint32_t* As = (uint32_t*)(smem + SO_A);
    uint32_t* Ws = (uint32_t*)(smem + SO_W);
    const int t = threadIdx.x;
    const int s = blockIdx.x % split;
    const int tile = blockIdx.x / split;
    const int cpb = nchunks / split;     // all chosen splits give integer cpb >= 2
    const int c0 = s * cpb, c1 = c0 + cpb;

#define STAGE(c)                                                                     \
    do {                                                                             \
        int _slot = (c) % 3;                                                         \
        uint32_t _wd = sbase + SO_W +                                                \
            (uint32_t)(_slot * 1152 + (t >> 4) * WP + (t & 15) * 4) * 4;             \
        CPA16(_wd, Wq + (size_t)(c) * 1024 + t * 4);                                 \
        if (t < 16)                                                                  \
            CPA16(sbase + SO_IDX + _slot * 256 + t * 16, idx + (c) * 64 + t * 4);    \
        CPCOMMIT();                                                                  \
    } while (0)

    STAGE(c0);
    STAGE(c0 + 1);   // cpb >= 2 always

    // ---- load L/R into T (bf16, m-pairs packed) + ones/zeros rows ----
    {
        int mp = t & 63, half = (t >> 6) & 1, fb = (t >> 7) * 32;
        int m0 = 2 * mp;
        const float *s0, *s1;
        if (mode == 1) {
            s0 = Xin + (size_t)(half * BATCH + tile * 128 + m0) * D + fb;
            s1 = s0 + D;
        } else if (mode == 2) {
            int g0 = tile * 128 + m0;
            int p0 = g0 & 31, bp0 = g0 >> 5;          // n_out = 32
            int tree = bp0 >> 10, b = bp0 & 1023;
            int leaf0 = 2 * p0 + half;
            const int* tbl = tree ? right : left;
            int v0i = __ldg(tbl + b * 64 + leaf0);
            int v1i = __ldg(tbl + b * 64 + leaf0 + 2);
            s0 = g_vocT + (size_t)v0i * D + fb;
            s1 = g_vocT + (size_t)v1i * D + fb;
        } else {
            int g0 = tile * 128 + m0, g1 = g0 + 1;
            int p0 = g0 % n_out, bp0 = g0 / n_out;
            int p1 = g1 % n_out, bp1 = g1 / n_out;
            s0 = Xin + (size_t)(bp0 * 2 * n_out + 2 * p0 + half) * D + fb;
            s1 = Xin + (size_t)(bp1 * 2 * n_out + 2 * p1 + half) * D + fb;
        }
#pragma unroll
        for (int j4 = 0; j4 < 32; j4 += 4) {
            float4 v0 = *(const float4*)(s0 + j4);
            float4 v1 = *(const float4*)(s1 + j4);
            if (mode == 2) {
                float4 bb = *(const float4*)(voc_b + fb + j4);
                v0.x += bb.x; v0.y += bb.y; v0.z += bb.z; v0.w += bb.w;
                v1.x += bb.x; v1.y += bb.y; v1.z += bb.z; v1.w += bb.w;
            }
            int fg = (half * 64 + fb + j4) * 64 + mp;
            Tw[fg]       = pack_bf16(v0.x, v1.x);
            Tw[fg + 64]  = pack_bf16(v0.y, v1.y);
            Tw[fg + 128] = pack_bf16(v0.z, v1.z);
            Tw[fg + 192] = pack_bf16(v0.w, v1.w);
        }
        if (t < 64) { Tw[128 * 64 + t] = 0x3F803F80u; Tw[129 * 64 + t] = 0u; }
    }

    const int l = t & 31, wid = t >> 5;
    const int qr = l >> 2, qc = l & 3;
    const int m0 = (wid & 3) * 32;
    const int n0 = (wid >> 2) * 32;
    const int mloc = t & 127;
    const int kh2 = (t >> 7) * 8;
    const char* Tm = (const char*)Tw + mloc * 2;

    float acc[2][4][4] = {};

#define AGEN(c)                                                                      \
    do {                                                                             \
        const int4* ix = (const int4*)(smem + SO_IDX + ((c) % 3) * 256) + kh2;       \
        uint32_t* Ad = As + ((c) & 1) * (16 * AP) + mloc;                            \
        _Pragma("unroll")                                                            \
        for (int q = 0; q < 8; q++) {                                                \
            int4 p = ix[q];                                                          \
            unsigned short a0 = *(const unsigned short*)(Tm + p.x);                  \
            unsigned short b0 = *(const unsigned short*)(Tm + p.y);                  \
            unsigned short a1 = *(const unsigned short*)(Tm + p.z);                  \
            unsigned short b1 = *(const unsigned short*)(Tm + p.w);                  \
            uint32_t av, bv, w;                                                      \
            asm("mov.b32 %0, {%1,%2};" : "=r"(av) : "h"(a0), "h"(a1));               \
            asm("mov.b32 %0, {%1,%2};" : "=r"(bv) : "h"(b0), "h"(b1));               \
            asm("mul.rn.bf16x2 %0, %1, %2;" : "=r"(w) : "r"(av), "r"(bv));           \
            Ad[(kh2 + q) * AP] = w;                                                  \
        }                                                                            \
    } while (0)

    CPWAIT(1);            // group c0 complete
    __syncthreads();
    AGEN(c0);

    for (int c = c0; c < c1; c++) {
        __syncthreads();  // A(c) visible; prior MMA reads of W slot done
        if (c + 2 < c1) {
            STAGE(c + 2);
            CPWAIT(1);    // group c+1 complete; c+2 in flight for a full chunk body
        } else {
            CPWAIT(0);
        }
        if (c + 1 < c1) AGEN(c + 1);

        const uint32_t* Ab = As + (c & 1) * (16 * AP);
        const uint32_t* Wb = Ws + (c % 3) * 1152;
#pragma unroll
        for (int ks = 0; ks < 2; ks++) {
            const uint32_t* ap = Ab + (ks * 8 + qc) * AP;
            uint32_t af[2][4];
#pragma unroll
            for (int mf = 0; mf < 2; mf++) {
                int r = m0 + mf * 16 + qr;
                af[mf][0] = ap[r];
                af[mf][1] = ap[r + 8];
                af[mf][2] = ap[4 * AP + r];
                af[mf][3] = ap[4 * AP + r + 8];
            }
            const uint32_t* bp = Wb + (ks * 8 + qc) * WP + n0 + qr;
#pragma unroll
            for (int nf = 0; nf < 4; nf++) {
                uint32_t b0 = bp[nf * 8];
                uint32_t b1 = bp[4 * WP + nf * 8];
                mma16(acc[0][nf], af[0], b0, b1);
                mma16(acc[1][nf], af[1], b0, b1);
            }
        }
    }

    // ---- epilogue ----
#pragma unroll
    for (int mf = 0; mf < 2; mf++) {
#pragma unroll
        for (int nf = 0; nf < 4; nf++) {
            int row = m0 + mf * 16 + qr;
            int col = n0 + nf * 8 + qc * 2;
            float* a4 = acc[mf][nf];
            if (split == 1) {
                float b0v = __ldg(e_bias + col), b1v = __ldg(e_bias + col + 1);
                float* dst = Xout + (size_t)(tile * 128 + row) * D + col;
                *(float2*)dst = make_float2(tanhf(a4[0] + b0v), tanhf(a4[1] + b1v));
                dst += 8 * D;
                *(float2*)dst = make_float2(tanhf(a4[2] + b0v), tanhf(a4[3] + b1v));
            } else {
                float* dst = outpart + (size_t)(s * ntiles + tile) * 8192 + row * 64 + col;
                *(float2*)dst = make_float2(a4[0], a4[1]);
                *(float2*)(dst + 8 * 64) = make_float2(a4[2], a4[3]);
            }
        }
    }
#undef STAGE
#undef AGEN
}

// -------- sum split partials + bias + tanh (vectorized) --------
__global__ void __launch_bounds__(256) k_reduce(const float* __restrict__ part,
                                                float* __restrict__ Xout,
                                                const float* __restrict__ bias,
                                                int ntiles, int split) {
    int tile = blockIdx.x;
    const float4* src = (const float4*)(part + (size_t)tile * 8192);
    float4* dst = (float4*)(Xout + (size_t)tile * 8192);
    size_t stride4 = (size_t)ntiles * 2048;
    for (int i4 = threadIdx.x; i4 < 2048; i4 += 256) {
        float4 v = src[i4];
        for (int sp = 1; sp < split; sp++) {
            float4 u = src[sp * stride4 + i4];
            v.x += u.x; v.y += u.y; v.z += u.z; v.w += u.w;
        }
        float4 bb = *(const float4*)(bias + (i4 & 15) * 4);
        v.x = tanhf(v.x + bb.x); v.y = tanhf(v.y + bb.y);
        v.z = tanhf(v.z + bb.z); v.w = tanhf(v.w + bb.w);
        dst[i4] = v;
    }
}

// -------- final epilogue: reduce + bias + leaky + logits + softmax --------
__global__ void __launch_bounds__(256) k_final_reduce(const float* __restrict__ part,
                                                      float* __restrict__ out,
                                                      const float* __restrict__ bias,
                                                      const float* __restrict__ sm_w,
                                                      const float* __restrict__ sm_b,
                                                      int split) {
    __shared__ float actT[64 * 132];
    const int tile = blockIdx.x;
    const int t = threadIdx.x;
    const int ntiles = BATCH / 128;

    const float4* src = (const float4*)(part + (size_t)tile * 8192);
    size_t stride4 = (size_t)ntiles * 2048;
    for (int i4 = t; i4 < 2048; i4 += 256) {
        float4 v = src[i4];
        for (int sp = 1; sp < split; sp++) {
            float4 u = src[sp * stride4 + i4];
            v.x += u.x; v.y += u.y; v.z += u.z; v.w += u.w;
        }
        float4 bb = *(const float4*)(bias + (i4 & 15) * 4);
        int m = i4 >> 4, c0 = (i4 & 15) * 4;
        float vv[4] = {v.x + bb.x, v.y + bb.y, v.z + bb.z, v.w + bb.w};
#pragma unroll
        for (int j = 0; j < 4; j++) {
            float a = vv[j];
            a = (a > 0.f) ? a : 0.01f * a;
            actT[(c0 + j) * 132 + m] = a;
        }
    }
    __syncthreads();

    if (t < 128) {
        int m = t;
        float lg[NREL];
#pragma unroll
        for (int c = 0; c < NREL; c++) {
            float ssum = sm_b[c];
#pragma unroll 8
            for (int e = 0; e < 64; e++) ssum += actT[e * 132 + m] * sm_w[c * 64 + e];
            lg[c] = ssum;
        }
        float mx = lg[0];
#pragma unroll
        for (int c = 1; c < NREL; c++) mx = fmaxf(mx, lg[c]);
        float sum = 0.f;
#pragma unroll
        for (int c = 0; c < NREL; c++) { lg[c] = expf(lg[c] - mx); sum += lg[c]; }
        float inv = 1.f / sum;
#pragma unroll
        for (int c = 0; c < NREL; c++) out[(tile * 128 + m) * NREL + c] = lg[c] * inv;
    }
}

// -------- launcher --------
extern "C" void kernel_launch(void* const* d_in, const int* in_sizes, int n_in,
                              void* d_out, int out_size) {
    (void)in_sizes; (void)n_in; (void)out_size;
    const int*   left   = (const int*)d_in[0];
    const int*   right  = (const int*)d_in[1];
    const float* voc_w  = (const float*)d_in[2];
    const float* voc_b  = (const float*)d_in[3];
    const float* cps_w  = (const float*)d_in[4];
    const float* cps_b  = (const float*)d_in[5];
    const float* cpst_w = (const float*)d_in[6];
    const float* cpst_b = (const float*)d_in[7];
    const float* cpr_w  = (const float*)d_in[8];
    const float* cpr_b  = (const float*)d_in[9];
    const float* cprt_w = (const float*)d_in[10];
    const float* cprt_b = (const float*)d_in[11];
    const float* sm_w   = (const float*)d_in[12];
    const float* sm_b   = (const float*)d_in[13];
    float* out = (float*)d_out;

    float *XA, *XB, *bc, *bf, *pA, *pB;
    uint32_t *Wc2, *Wf2;
    int *idxC, *idxF;
    cudaGetSymbolAddress((void**)&XA, g_XA);
    cudaGetSymbolAddress((void**)&XB, g_XB);
    cudaGetSymbolAddress((void**)&Wc2, g_Wc2);
    cudaGetSymbolAddress((void**)&Wf2, g_Wf2);
    cudaGetSymbolAddress((void**)&bc, g_bc);
    cudaGetSymbolAddress((void**)&bf, g_bf);
    cudaGetSymbolAddress((void**)&pA, g_partA);
    cudaGetSymbolAddress((void**)&pB, g_partB);
    cudaGetSymbolAddress((void**)&idxC, g_idxC);
    cudaGetSymbolAddress((void**)&idxF, g_idxF);

    cudaFuncSetAttribute(k_gemm, cudaFuncAttributeMaxDynamicSharedMemorySize, SMEM_BYTES);

    k_transpose_voc<<<(VOC + 63) / 64, 256>>>(voc_w);
    k_prep<<<NCHC + NCHF + 3, 256>>>(cps_w, cps_b, cpst_w, cpst_b,
                                     cpr_w, cpr_b, cprt_w, cprt_b);

    // L1 (vocab gather): 512 tiles, split 2 (1024 blocks) -> pA
    k_gemm<<<1024, 256, SMEM_BYTES>>>(nullptr, nullptr, pA, Wc2, idxC, bc,
                                      left, right, voc_b, 32, NCHC, 2, 512, 2);
    k_reduce<<<512, 256>>>(pA, XB, bc, 512, 2);
    // L2: 256 tiles, split 5 (1280 blocks) -> pB
    k_gemm<<<1280, 256, SMEM_BYTES>>>(XB, nullptr, pB, Wc2, idxC, bc,
                                      left, right, voc_b, 16, NCHC, 5, 256, 0);
    k_reduce<<<256, 256>>>(pB, XA, bc, 256, 5);
    // L3: 128 tiles, split 2 (256 blocks) -> pA
    k_gemm<<<256, 256, SMEM_BYTES>>>(XA, nullptr, pA, Wc2, idxC, bc,
                                     left, right, voc_b, 8, NCHC, 2, 128, 0);
    k_reduce<<<128, 256>>>(pA, XB, bc, 128, 2);
    // L4: 64 tiles, split 5 (320 blocks) -> pB
    k_gemm<<<320, 256, SMEM_BYTES>>>(XB, nullptr, pB, Wc2, idxC, bc,
                                     left, right, voc_b, 4, NCHC, 5, 64, 0);
    k_reduce<<<64, 256>>>(pB, XA, bc, 64, 5);
    // L5: 32 tiles, split 10 (320 blocks) -> pA
    k_gemm<<<320, 256, SMEM_BYTES>>>(XA, nullptr, pA, Wc2, idxC, bc,
                                     left, right, voc_b, 2, NCHC, 10, 32, 0);
    k_reduce<<<32, 256>>>(pA, XB, bc, 32, 10);
    // L6: 16 tiles, split 14 (224 blocks) -> pB
    k_gemm<<<224, 256, SMEM_BYTES>>>(XB, nullptr, pB, Wc2, idxC, bc,
                                     left, right, voc_b, 1, NCHC, 14, 16, 0);
    k_reduce<<<16, 256>>>(pB, XA, bc, 16, 14);
    // final: 8 tiles, split 33 (264 blocks) -> pA
    k_gemm<<<264, 256, SMEM_BYTES>>>(XA, nullptr, pA, Wf2, idxF, bf,
                                     left, right, voc_b, 1, NCHF, 33, 8, 1);
    k_final_reduce<<<BATCH / 128, 256>>>(pA, out, bf, sm_w, sm_b, 33);
}

// round 13
// speedup vs baseline: 1.7972x; 1.1093x over previous
#include <cuda_runtime.h>
#include <cuda_bf16.h>
#include <math.h>
#include <cstdint>

#define BATCH 1024
#define D     64
#define VOC   50000
#define NREL  7
#define KC    2240      // compose: 2112 padded-triangular + 128 linear
#define NCHC  70
#define KF    4224      // final: 4096 kron + 128 linear
#define NCHF  132

// smem byte layout (total 69632 B -> 3 CTAs/SM, 208.9KB of 228KB)
#define SO_IDX 0           // 3 x 128 B idx slots (16 pairs x 8 B)
#define SO_T   512         // T bf16 [128 m][260 B] = 33280 B (130 f, 65-word pitch)
#define SO_A   33792       // 2 x (128 m x 80 B) = 20480 B (16 k2 words + pad, pitch 20)
#define SO_W   54272       // 3 x (64 e x 80 B) = 15360 B (16 k2 words + pad, pitch 20)
#define SMEM_BYTES 69632

// -------- device scratch --------
__device__ float    g_vocT[VOC * D];
__device__ float    g_XA[2 * BATCH * 16 * D];
__device__ float    g_XB[2 * BATCH * 32 * D];
__device__ uint32_t g_Wc2[NCHC * 1024];   // bf16x2 W chunks [c][e*16 + k2]
__device__ uint32_t g_Wf2[NCHF * 1024];
__device__ int      g_idxC[KC];           // per PAIR: (a_off, b_off) byte offsets
__device__ int      g_idxF[KF];
__device__ float    g_bc[D];
__device__ float    g_bf[D];
__device__ float    g_partA[1024 * 8192];
__device__ float    g_partB[1280 * 8192];

// -------- PTX helpers --------
__device__ __forceinline__ uint32_t s2u(const void* p) {
    uint32_t a;
    asm("{.reg .u64 t; cvta.to.shared.u64 t, %1; cvt.u32.u64 %0, t;}" : "=r"(a) : "l"(p));
    return a;
}
__device__ __forceinline__ void mma16(float* d, const uint32_t* a, uint32_t b0, uint32_t b1) {
    asm volatile(
        "mma.sync.aligned.m16n8k16.row.col.f32.bf16.bf16.f32 "
        "{%0,%1,%2,%3},{%4,%5,%6,%7},{%8,%9},{%0,%1,%2,%3};"
        : "+f"(d[0]), "+f"(d[1]), "+f"(d[2]), "+f"(d[3])
        : "r"(a[0]), "r"(a[1]), "r"(a[2]), "r"(a[3]), "r"(b0), "r"(b1));
}
__device__ __forceinline__ uint32_t pack_bf16(float lo, float hi) {
    uint32_t d;
    asm("cvt.rn.bf16x2.f32 %0, %1, %2;" : "=r"(d) : "f"(hi), "f"(lo));
    return d;
}
#define LDSM4(R, addr)                                                        \
    asm volatile("ldmatrix.sync.aligned.m8n8.x4.shared.b16 {%0,%1,%2,%3}, [%4];" \
        : "=r"((R)[0]), "=r"((R)[1]), "=r"((R)[2]), "=r"((R)[3]) : "r"(addr))
#define CPA16(dst, src) \
    asm volatile("cp.async.ca.shared.global [%0], [%1], 16;" :: "r"(dst), "l"(src))
#define CPCOMMIT() asm volatile("cp.async.commit_group;")
#define CPWAIT(n)  asm volatile("cp.async.wait_group %0;" :: "n"(n) : "memory")

// -------- vocab transpose --------
__global__ void k_transpose_voc(const float* __restrict__ voc_w) {
    __shared__ float tile[64][65];
    int v0 = blockIdx.x * 64;
    for (int idx = threadIdx.x; idx < 64 * 64; idx += 256) {
        int d = idx >> 6, vv = idx & 63;
        int v = v0 + vv;
        tile[vv][d] = (v < VOC) ? voc_w[d * VOC + v] : 0.f;
    }
    __syncthreads();
    for (int idx = threadIdx.x; idx < 64 * 64; idx += 256) {
        int vv = idx >> 6, d = idx & 63;
        int v = v0 + vv;
        if (v < VOC) g_vocT[v * D + d] = tile[vv][d];
    }
}

// -------- padded-triangular enumeration --------
// row i padded to even length; start(i) in k-slots
__device__ __forceinline__ int startP(int i) {
    int m = i >> 1;
    return (i & 1) ? 2 * (m + 1) * (m + 1) : 2 * m * (m + 1);
}
__device__ __forceinline__ int rowP(int k) {   // find i with startP(i) <= k < startP(i+1)
    int i = (int)sqrtf(2.f * (float)k + 1.f);
    if (i > 63) i = 63;
    while (startP(i) > k) i--;
    while (i < 63 && startP(i + 1) <= k) i++;
    return i;
}
__device__ __forceinline__ float wcomp(const float* cpst_w, const float* cps_w, int k, int e) {
    if (k < 2112) {
        int i = rowP(k);
        int j = k - startP(i);
        if (j < i)  return cpst_w[e * 4096 + i * 64 + j] + cpst_w[e * 4096 + j * 64 + i];
        if (j == i) return cpst_w[e * 4096 + i * 65];
        return 0.f;     // pad slot
    }
    return cps_w[e * 128 + (k - 2112)];
}

__global__ void k_prep(const float* __restrict__ cps_w,  const float* __restrict__ cps_b,
                       const float* __restrict__ cpst_w, const float* __restrict__ cpst_b,
                       const float* __restrict__ cpr_w,  const float* __restrict__ cpr_b,
                       const float* __restrict__ cprt_w, const float* __restrict__ cprt_b) {
    int blk = blockIdx.x, t = threadIdx.x;
    if (blk < NCHC) {                        // compose W chunks [e][k2]
        int c = blk;
        for (int u = t; u < 1024; u += 256) {
            int e = u >> 4, k2 = u & 15;
            int k = c * 32 + 2 * k2;
            g_Wc2[c * 1024 + u] = pack_bf16(wcomp(cpst_w, cps_w, k, e),
                                            wcomp(cpst_w, cps_w, k + 1, e));
        }
    } else if (blk < NCHC + NCHF) {          // final W chunks [e][k2]
        int c = blk - NCHC;
        for (int u = t; u < 1024; u += 256) {
            int e = u >> 4, k2 = u & 15;
            int k = c * 32 + 2 * k2;
            float v0 = (k < 4096) ? cprt_w[e * 4096 + k] : cpr_w[e * 128 + (k - 4096)];
            float v1 = (k + 1 < 4096) ? cprt_w[e * 4096 + k + 1] : cpr_w[e * 128 + (k + 1 - 4096)];
            g_Wf2[c * 1024 + u] = pack_bf16(v0, v1);
        }
    } else if (blk == NCHC + NCHF) {         // biases
        if (t < D) {
            g_bc[t] = cps_b[t] + cpst_b[t];
            g_bf[t] = cpr_b[t] + cprt_b[t];
        }
    } else if (blk == NCHC + NCHF + 1) {     // compose idx: per-pair byte offsets in T row
        for (int p = t; p < KC / 2; p += 256) {
            int k = 2 * p;
            int a_off, b_off;
            if (k < 2112) {
                int i = rowP(k);
                a_off = i * 2;
                b_off = (k - startP(i)) * 2;
            } else {
                a_off = 128 * 2;              // ones slot
                b_off = (k - 2112) * 2;
            }
            g_idxC[p * 2] = a_off;
            g_idxC[p * 2 + 1] = b_off;
        }
    } else {                                 // final idx
        for (int p = t; p < KF / 2; p += 256) {
            int k = 2 * p;
            int a_off, b_off;
            if (k < 4096) {
                a_off = (k >> 6) * 2;
                b_off = (64 + (k & 63)) * 2;
            } else {
                a_off = 128 * 2;
                b_off = (k - 4096) * 2;
            }
            g_idxF[p * 2] = a_off;
            g_idxF[p * 2 + 1] = b_off;
        }
    }
}

// -------- pipelined bf16 tensor GEMM level --------
// mode: 0 compose, 1 final, 2 level1 (fused vocab gather)
__global__ void __launch_bounds__(256, 3) k_gemm(const float* __restrict__ Xin,
                                                 float* __restrict__ outpart,
                                                 const uint32_t* __restrict__ Wq,
                                                 const int* __restrict__ idx,
                                                 const float* __restrict__ e_bias,
                                                 const int* __restrict__ left,
                                                 const int* __restrict__ right,
                                                 const float* __restrict__ voc_b,
                                                 float* __restrict__ Xout,
                                                 int n_out, int nchunks, int split,
                                                 int ntiles, int mode) {
    extern __shared__ char smem[];
    const uint32_t sbase = s2u(smem);
    const int t = threadIdx.x;
    const int s = blockIdx.x % split;
    const int tile = blockIdx.x / split;
    const int cpb = nchunks / split;
    const int c0 = s * cpb, c1 = c0 + cpb;

#define STAGE(c)                                                                      \
    do {                                                                              \
        int _slot = (c) % 3;                                                          \
        uint32_t _wd = sbase + SO_W +                                                 \
            (uint32_t)(_slot * 5120 + (t >> 2) * 80 + (t & 3) * 16);                  \
        CPA16(_wd, Wq + (size_t)(c) * 1024 + t * 4);                                  \
        if (t < 8)                                                                    \
            CPA16(sbase + SO_IDX + _slot * 128 + t * 16, idx + (c) * 32 + t * 4);     \
        CPCOMMIT();                                                                   \
    } while (0)

    STAGE(c0);
    STAGE(c0 + 1);   // cpb >= 2 always

    // ---- load L/R into T[m][f] bf16 rows + ones/zero pair ----
    {
        int m = t & 127, half = t >> 7;
        const float* src;
        if (mode == 1) {
            src = Xin + (size_t)(half * BATCH + tile * 128 + m) * D;
        } else if (mode == 2) {
            int g = tile * 128 + m;
            int p = g & 31, bp = g >> 5;              // n_out = 32
            int tree = bp >> 10, b = bp & 1023;
            const int* tbl = tree ? right : left;
            int vi = __ldg(tbl + b * 64 + 2 * p + half);
            src = g_vocT + (size_t)vi * D;
        } else {
            int g = tile * 128 + m;
            int p = g % n_out, bp = g / n_out;
            src = Xin + (size_t)(bp * 2 * n_out + 2 * p + half) * D;
        }
        char* Td = smem + SO_T + m * 260 + half * 128;
#pragma unroll
        for (int it = 0; it < 16; it++) {
            float4 v = *(const float4*)(src + it * 4);
            if (mode == 2) {
                float4 bb = *(const float4*)(voc_b + it * 4);
                v.x += bb.x; v.y += bb.y; v.z += bb.z; v.w += bb.w;
            }
            *(uint32_t*)(Td + it * 8)     = pack_bf16(v.x, v.y);
            *(uint32_t*)(Td + it * 8 + 4) = pack_bf16(v.z, v.w);
        }
        if (t < 128) *(uint32_t*)(smem + SO_T + t * 260 + 256) = 0x00003F80u; // (1.0, 0)
    }

    const int l = t & 31, wid = t >> 5;
    const int qr = l >> 2, qc = l & 3;
    const int m0 = (wid & 3) * 32;
    const int n0 = (wid >> 2) * 32;
    const int mloc = t & 127;
    const int kh2 = (t >> 7) * 8;                 // pair offset (0 or 8)
    const char* Trow = smem + SO_T + mloc * 260;

    // ldmatrix lane addressing (x4 tile order per fragment-layout derivation)
    const int lt = l >> 3, lr = l & 7;
    const uint32_t a_lane = (uint32_t)((m0 + ((lt & 1) << 3) + lr) * 80 + ((lt >> 1) << 4));
    const uint32_t b_lane = (uint32_t)((n0 + ((lt >> 1) << 3) + lr) * 80 + ((lt & 1) << 4));

    float acc[2][4][4] = {};

#define AGEN(c)                                                                       \
    do {                                                                              \
        const int4* ix4 = (const int4*)(smem + SO_IDX + ((c) % 3) * 128) + (kh2 >> 1);\
        uint32_t* Ad = (uint32_t*)(smem + SO_A + ((c) & 1) * 10240) + mloc * 20 + kh2;\
        uint32_t w[8];                                                                \
        _Pragma("unroll")                                                             \
        for (int qq = 0; qq < 4; qq++) {                                              \
            int4 pp = ix4[qq];                                                        \
            unsigned short a0 = *(const unsigned short*)(Trow + pp.x);                \
            uint32_t bv0 = *(const uint32_t*)(Trow + pp.y);                           \
            unsigned short a1 = *(const unsigned short*)(Trow + pp.z);                \
            uint32_t bv1 = *(const uint32_t*)(Trow + pp.w);                           \
            uint32_t ad0, ad1;                                                        \
            asm("mov.b32 %0, {%1,%1};" : "=r"(ad0) : "h"(a0));                        \
            asm("mov.b32 %0, {%1,%1};" : "=r"(ad1) : "h"(a1));                        \
            asm("mul.rn.bf16x2 %0, %1, %2;" : "=r"(w[qq * 2])     : "r"(ad0), "r"(bv0)); \
            asm("mul.rn.bf16x2 %0, %1, %2;" : "=r"(w[qq * 2 + 1]) : "r"(ad1), "r"(bv1)); \
        }                                                                             \
        *(uint4*)Ad       = make_uint4(w[0], w[1], w[2], w[3]);                       \
        *(uint4*)(Ad + 4) = make_uint4(w[4], w[5], w[6], w[7]);                       \
    } while (0)

    CPWAIT(1);            // group c0 complete
    __syncthreads();
    AGEN(c0);

    for (int c = c0; c < c1; c++) {
        __syncthreads();  // A(c) visible; prior frag reads of slots done
        if (c + 2 < c1) {
            STAGE(c + 2);
            CPWAIT(1);    // group c+1 complete; c+2 in flight for a full chunk body
        } else {
            CPWAIT(0);
        }
        if (c + 1 < c1) AGEN(c + 1);

        const uint32_t Ab = sbase + SO_A + (uint32_t)((c & 1) * 10240) + a_lane;
        const uint32_t Wb = sbase + SO_W + (uint32_t)((c % 3) * 5120) + b_lane;
#pragma unroll
        for (int ks = 0; ks < 2; ks++) {
            uint32_t a0[4], a1[4], b01[4], b23[4];
            LDSM4(a0, Ab + ks * 32);           // m rows m0..m0+15
            LDSM4(a1, Ab + 1280 + ks * 32);    // m rows m0+16..m0+31
            LDSM4(b01, Wb + ks * 32);          // nf 0,1
            LDSM4(b23, Wb + 1280 + ks * 32);   // nf 2,3
            mma16(acc[0][0], a0, b01[0], b01[1]);
            mma16(acc[0][1], a0, b01[2], b01[3]);
            mma16(acc[0][2], a0, b23[0], b23[1]);
            mma16(acc[0][3], a0, b23[2], b23[3]);
            mma16(acc[1][0], a1, b01[0], b01[1]);
            mma16(acc[1][1], a1, b01[2], b01[3]);
            mma16(acc[1][2], a1, b23[0], b23[1]);
            mma16(acc[1][3], a1, b23[2], b23[3]);
        }
    }

    // ---- epilogue ----
#pragma unroll
    for (int mf = 0; mf < 2; mf++) {
#pragma unroll
        for (int nf = 0; nf < 4; nf++) {
            int row = m0 + mf * 16 + qr;
            int col = n0 + nf * 8 + qc * 2;
            float* a4 = acc[mf][nf];
            if (split == 1) {
                float b0v = __ldg(e_bias + col), b1v = __ldg(e_bias + col + 1);
                float* dst = Xout + (size_t)(tile * 128 + row) * D + col;
                *(float2*)dst = make_float2(tanhf(a4[0] + b0v), tanhf(a4[1] + b1v));
                dst += 8 * D;
                *(float2*)dst = make_float2(tanhf(a4[2] + b0v), tanhf(a4[3] + b1v));
            } else {
                float* dst = outpart + (size_t)(s * ntiles + tile) * 8192 + row * 64 + col;
                *(float2*)dst = make_float2(a4[0], a4[1]);
                *(float2*)(dst + 8 * 64) = make_float2(a4[2], a4[3]);
            }
        }
    }
#undef STAGE
#undef AGEN
}

// -------- sum split partials + bias + tanh --------
__global__ void __launch_bounds__(256) k_reduce(const float* __restrict__ part,
                                                float* __restrict__ Xout,
                                                const float* __restrict__ bias,
                                                int ntiles, int split) {
    int tile = blockIdx.x;
    const float4* src = (const float4*)(part + (size_t)tile * 8192);
    float4* dst = (float4*)(Xout + (size_t)tile * 8192);
    size_t stride4 = (size_t)ntiles * 2048;
    for (int i4 = threadIdx.x; i4 < 2048; i4 += 256) {
        float4 v = src[i4];
        for (int sp = 1; sp < split; sp++) {
            float4 u = src[sp * stride4 + i4];
            v.x += u.x; v.y += u.y; v.z += u.z; v.w += u.w;
        }
        float4 bb = *(const float4*)(bias + (i4 & 15) * 4);
        v.x = tanhf(v.x + bb.x); v.y = tanhf(v.y + bb.y);
        v.z = tanhf(v.z + bb.z); v.w = tanhf(v.w + bb.w);
        dst[i4] = v;
    }
}

// -------- final epilogue: reduce + bias + leaky + logits + softmax --------
__global__ void __launch_bounds__(256) k_final_reduce(const float* __restrict__ part,
                                                      float* __restrict__ out,
                                                      const float* __restrict__ bias,
                                                      const float* __restrict__ sm_w,
                                                      const float* __restrict__ sm_b,
                                                      int split) {
    __shared__ float actT[64 * 132];
    const int tile = blockIdx.x;
    const int t = threadIdx.x;
    const int ntiles = BATCH / 128;

    const float4* src = (const float4*)(part + (size_t)tile * 8192);
    size_t stride4 = (size_t)ntiles * 2048;
    for (int i4 = t; i4 < 2048; i4 += 256) {
        float4 v = src[i4];
        for (int sp = 1; sp < split; sp++) {
            float4 u = src[sp * stride4 + i4];
            v.x += u.x; v.y += u.y; v.z += u.z; v.w += u.w;
        }
        float4 bb = *(const float4*)(bias + (i4 & 15) * 4);
        int m = i4 >> 4, c0 = (i4 & 15) * 4;
        float vv[4] = {v.x + bb.x, v.y + bb.y, v.z + bb.z, v.w + bb.w};
#pragma unroll
        for (int j = 0; j < 4; j++) {
            float a = vv[j];
            a = (a > 0.f) ? a : 0.01f * a;
            actT[(c0 + j) * 132 + m] = a;
        }
    }
    __syncthreads();

    if (t < 128) {
        int m = t;
        float lg[NREL];
#pragma unroll
        for (int c = 0; c < NREL; c++) {
            float ssum = sm_b[c];
#pragma unroll 8
            for (int e = 0; e < 64; e++) ssum += actT[e * 132 + m] * sm_w[c * 64 + e];
            lg[c] = ssum;
        }
        float mx = lg[0];
#pragma unroll
        for (int c = 1; c < NREL; c++) mx = fmaxf(mx, lg[c]);
        float sum = 0.f;
#pragma unroll
        for (int c = 0; c < NREL; c++) { lg[c] = expf(lg[c] - mx); sum += lg[c]; }
        float inv = 1.f / sum;
#pragma unroll
        for (int c = 0; c < NREL; c++) out[(tile * 128 + m) * NREL + c] = lg[c] * inv;
    }
}

// -------- launcher --------
extern "C" void kernel_launch(void* const* d_in, const int* in_sizes, int n_in,
                              void* d_out, int out_size) {
    (void)in_sizes; (void)n_in; (void)out_size;
    const int*   left   = (const int*)d_in[0];
    const int*   right  = (const int*)d_in[1];
    const float* voc_w  = (const float*)d_in[2];
    const float* voc_b  = (const float*)d_in[3];
    const float* cps_w  = (const float*)d_in[4];
    const float* cps_b  = (const float*)d_in[5];
    const float* cpst_w = (const float*)d_in[6];
    const float* cpst_b = (const float*)d_in[7];
    const float* cpr_w  = (const float*)d_in[8];
    const float* cpr_b  = (const float*)d_in[9];
    const float* cprt_w = (const float*)d_in[10];
    const float* cprt_b = (const float*)d_in[11];
    const float* sm_w   = (const float*)d_in[12];
    const float* sm_b   = (const float*)d_in[13];
    float* out = (float*)d_out;

    float *XA, *XB, *bc, *bf, *pA, *pB;
    uint32_t *Wc2, *Wf2;
    int *idxC, *idxF;
    cudaGetSymbolAddress((void**)&XA, g_XA);
    cudaGetSymbolAddress((void**)&XB, g_XB);
    cudaGetSymbolAddress((void**)&Wc2, g_Wc2);
    cudaGetSymbolAddress((void**)&Wf2, g_Wf2);
    cudaGetSymbolAddress((void**)&bc, g_bc);
    cudaGetSymbolAddress((void**)&bf, g_bf);
    cudaGetSymbolAddress((void**)&pA, g_partA);
    cudaGetSymbolAddress((void**)&pB, g_partB);
    cudaGetSymbolAddress((void**)&idxC, g_idxC);
    cudaGetSymbolAddress((void**)&idxF, g_idxF);

    cudaFuncSetAttribute(k_gemm, cudaFuncAttributeMaxDynamicSharedMemorySize, SMEM_BYTES);

    k_transpose_voc<<<(VOC + 63) / 64, 256>>>(voc_w);
    k_prep<<<NCHC + NCHF + 3, 256>>>(cps_w, cps_b, cpst_w, cpst_b,
                                     cpr_w, cpr_b, cprt_w, cprt_b);

    // L1 (vocab gather): 512 tiles, split 2 (1024 blocks) -> pA
    k_gemm<<<1024, 256, SMEM_BYTES>>>(nullptr, pA, Wc2, idxC, bc,
                                      left, right, voc_b, nullptr, 32, NCHC, 2, 512, 2);
    k_reduce<<<512, 256>>>(pA, XB, bc, 512, 2);
    // L2: 256 tiles, split 5 (1280 blocks) -> pB
    k_gemm<<<1280, 256, SMEM_BYTES>>>(XB, pB, Wc2, idxC, bc,
                                      left, right, voc_b, nullptr, 16, NCHC, 5, 256, 0);
    k_reduce<<<256, 256>>>(pB, XA, bc, 256, 5);
    // L3: 128 tiles, split 2 (256 blocks) -> pA
    k_gemm<<<256, 256, SMEM_BYTES>>>(XA, pA, Wc2, idxC, bc,
                                     left, right, voc_b, nullptr, 8, NCHC, 2, 128, 0);
    k_reduce<<<128, 256>>>(pA, XB, bc, 128, 2);
    // L4: 64 tiles, split 5 (320 blocks) -> pB
    k_gemm<<<320, 256, SMEM_BYTES>>>(XB, pB, Wc2, idxC, bc,
                                     left, right, voc_b, nullptr, 4, NCHC, 5, 64, 0);
    k_reduce<<<64, 256>>>(pB, XA, bc, 64, 5);
    // L5: 32 tiles, split 10 (320 blocks) -> pA
    k_gemm<<<320, 256, SMEM_BYTES>>>(XA, pA, Wc2, idxC, bc,
                                     left, right, voc_b, nullptr, 2, NCHC, 10, 32, 0);
    k_reduce<<<32, 256>>>(pA, XB, bc, 32, 10);
    // L6: 16 tiles, split 14 (224 blocks) -> pB
    k_gemm<<<224, 256, SMEM_BYTES>>>(XB, pB, Wc2, idxC, bc,
                                     left, right, voc_b, nullptr, 1, NCHC, 14, 16, 0);
    k_reduce<<<16, 256>>>(pB, XA, bc, 16, 14);
    // final: 8 tiles, split 33 (264 blocks) -> pA
    k_gemm<<<264, 256, SMEM_BYTES>>>(XA, pA, Wf2, idxF, bf,
                                     left, right, voc_b, nullptr, 1, NCHF, 33, 8, 1);
    k_final_reduce<<<BATCH / 128, 256>>>(pA, out, bf, sm_w, sm_b, 33);
}

// round 14
// speedup vs baseline: 1.8575x; 1.0336x over previous
#include <cuda_runtime.h>
#include <cuda_bf16.h>
#include <math.h>
#include <cstdint>

#define BATCH 1024
#define D     64
#define VOC   50000
#define NREL  7
#define KC    2240      // compose: 2112 padded-triangular + 128 linear
#define NCHC  70
#define KF    4224      // final: 4096 kron + 128 linear
#define NCHF  132

// smem byte layout (total 69632 B -> 3 CTAs/SM)
#define SO_IDX 0           // 3 x 128 B idx slots
#define SO_T   512         // T bf16 [128 m][260 B] = 33280 B; reused as actT[128][65] f32
#define SO_A   33792       // 2 x (128 m x 80 B) = 20480 B
#define SO_W   54272       // 3 x (64 e x 80 B) = 15360 B
#define SMEM_BYTES 69632

// -------- device scratch --------
__device__ float    g_vocT[VOC * D];
__device__ float    g_XA[2 * BATCH * 16 * D];
__device__ float    g_XB[2 * BATCH * 32 * D];
__device__ uint32_t g_Wc2[NCHC * 1024];   // bf16x2 W chunks [c][e*16 + k2]
__device__ uint32_t g_Wf2[NCHF * 1024];
__device__ int      g_idxC[KC];           // per PAIR: (a_off, b_off) byte offsets
__device__ int      g_idxF[KF];
__device__ float    g_bc[D];
__device__ float    g_bf[D];
__device__ float    g_partA[1024 * 8192];
__device__ float    g_partB[1280 * 8192];
__device__ int      g_cnt[512];           // per-tile arrival counters (self-resetting)

// -------- PTX helpers --------
__device__ __forceinline__ uint32_t s2u(const void* p) {
    uint32_t a;
    asm("{.reg .u64 t; cvta.to.shared.u64 t, %1; cvt.u32.u64 %0, t;}" : "=r"(a) : "l"(p));
    return a;
}
__device__ __forceinline__ void mma16(float* d, const uint32_t* a, uint32_t b0, uint32_t b1) {
    asm volatile(
        "mma.sync.aligned.m16n8k16.row.col.f32.bf16.bf16.f32 "
        "{%0,%1,%2,%3},{%4,%5,%6,%7},{%8,%9},{%0,%1,%2,%3};"
        : "+f"(d[0]), "+f"(d[1]), "+f"(d[2]), "+f"(d[3])
        : "r"(a[0]), "r"(a[1]), "r"(a[2]), "r"(a[3]), "r"(b0), "r"(b1));
}
__device__ __forceinline__ uint32_t pack_bf16(float lo, float hi) {
    uint32_t d;
    asm("cvt.rn.bf16x2.f32 %0, %1, %2;" : "=r"(d) : "f"(hi), "f"(lo));
    return d;
}
#define LDSM4(R, addr)                                                        \
    asm volatile("ldmatrix.sync.aligned.m8n8.x4.shared.b16 {%0,%1,%2,%3}, [%4];" \
        : "=r"((R)[0]), "=r"((R)[1]), "=r"((R)[2]), "=r"((R)[3]) : "r"(addr))
#define CPA16(dst, src) \
    asm volatile("cp.async.ca.shared.global [%0], [%1], 16;" :: "r"(dst), "l"(src))
#define CPCOMMIT() asm volatile("cp.async.commit_group;")
#define CPWAIT(n)  asm volatile("cp.async.wait_group %0;" :: "n"(n) : "memory")

// -------- vocab transpose --------
__global__ void k_transpose_voc(const float* __restrict__ voc_w) {
    __shared__ float tile[64][65];
    int v0 = blockIdx.x * 64;
    for (int idx = threadIdx.x; idx < 64 * 64; idx += 256) {
        int d = idx >> 6, vv = idx & 63;
        int v = v0 + vv;
        tile[vv][d] = (v < VOC) ? voc_w[d * VOC + v] : 0.f;
    }
    __syncthreads();
    for (int idx = threadIdx.x; idx < 64 * 64; idx += 256) {
        int vv = idx >> 6, d = idx & 63;
        int v = v0 + vv;
        if (v < VOC) g_vocT[v * D + d] = tile[vv][d];
    }
}

// -------- padded-triangular enumeration --------
__device__ __forceinline__ int startP(int i) {
    int m = i >> 1;
    return (i & 1) ? 2 * (m + 1) * (m + 1) : 2 * m * (m + 1);
}
__device__ __forceinline__ int rowP(int k) {
    int i = (int)sqrtf(2.f * (float)k + 1.f);
    if (i > 63) i = 63;
    while (startP(i) > k) i--;
    while (i < 63 && startP(i + 1) <= k) i++;
    return i;
}
__device__ __forceinline__ float wcomp(const float* cpst_w, const float* cps_w, int k, int e) {
    if (k < 2112) {
        int i = rowP(k);
        int j = k - startP(i);
        if (j < i)  return cpst_w[e * 4096 + i * 64 + j] + cpst_w[e * 4096 + j * 64 + i];
        if (j == i) return cpst_w[e * 4096 + i * 65];
        return 0.f;     // pad slot
    }
    return cps_w[e * 128 + (k - 2112)];
}

__global__ void k_prep(const float* __restrict__ cps_w,  const float* __restrict__ cps_b,
                       const float* __restrict__ cpst_w, const float* __restrict__ cpst_b,
                       const float* __restrict__ cpr_w,  const float* __restrict__ cpr_b,
                       const float* __restrict__ cprt_w, const float* __restrict__ cprt_b) {
    int blk = blockIdx.x, t = threadIdx.x;
    if (blk < NCHC) {                        // compose W chunks [e][k2]
        int c = blk;
        for (int u = t; u < 1024; u += 256) {
            int e = u >> 4, k2 = u & 15;
            int k = c * 32 + 2 * k2;
            g_Wc2[c * 1024 + u] = pack_bf16(wcomp(cpst_w, cps_w, k, e),
                                            wcomp(cpst_w, cps_w, k + 1, e));
        }
    } else if (blk < NCHC + NCHF) {          // final W chunks [e][k2]
        int c = blk - NCHC;
        for (int u = t; u < 1024; u += 256) {
            int e = u >> 4, k2 = u & 15;
            int k = c * 32 + 2 * k2;
            float v0 = (k < 4096) ? cprt_w[e * 4096 + k] : cpr_w[e * 128 + (k - 4096)];
            float v1 = (k + 1 < 4096) ? cprt_w[e * 4096 + k + 1] : cpr_w[e * 128 + (k + 1 - 4096)];
            g_Wf2[c * 1024 + u] = pack_bf16(v0, v1);
        }
    } else if (blk == NCHC + NCHF) {         // biases
        if (t < D) {
            g_bc[t] = cps_b[t] + cpst_b[t];
            g_bf[t] = cpr_b[t] + cprt_b[t];
        }
    } else if (blk == NCHC + NCHF + 1) {     // compose idx
        for (int p = t; p < KC / 2; p += 256) {
            int k = 2 * p;
            int a_off, b_off;
            if (k < 2112) {
                int i = rowP(k);
                a_off = i * 2;
                b_off = (k - startP(i)) * 2;
            } else {
                a_off = 128 * 2;
                b_off = (k - 2112) * 2;
            }
            g_idxC[p * 2] = a_off;
            g_idxC[p * 2 + 1] = b_off;
        }
    } else {                                 // final idx
        for (int p = t; p < KF / 2; p += 256) {
            int k = 2 * p;
            int a_off, b_off;
            if (k < 4096) {
                a_off = (k >> 6) * 2;
                b_off = (64 + (k & 63)) * 2;
            } else {
                a_off = 128 * 2;
                b_off = (k - 4096) * 2;
            }
            g_idxF[p * 2] = a_off;
            g_idxF[p * 2 + 1] = b_off;
        }
    }
}

// -------- pipelined bf16 tensor GEMM level + fused last-block reduction --------
// mode: 0 compose, 1 final, 2 level1 (fused vocab gather)
__global__ void __launch_bounds__(256, 3) k_gemm(const float* __restrict__ Xin,
                                                 float* __restrict__ outpart,
                                                 const uint32_t* __restrict__ Wq,
                                                 const int* __restrict__ idx,
                                                 const float* __restrict__ e_bias,
                                                 const int* __restrict__ left,
                                                 const int* __restrict__ right,
                                                 const float* __restrict__ voc_b,
                                                 float* __restrict__ Xout,
                                                 const float* __restrict__ sm_w,
                                                 const float* __restrict__ sm_b,
                                                 int n_out, int nchunks, int split,
                                                 int ntiles, int mode) {
    extern __shared__ char smem[];
    __shared__ int s_is_last;
    const uint32_t sbase = s2u(smem);
    const int t = threadIdx.x;
    const int s = blockIdx.x % split;
    const int tile = blockIdx.x / split;
    const int cpb = nchunks / split;
    const int c0 = s * cpb, c1 = c0 + cpb;

#define STAGE(c)                                                                      \
    do {                                                                              \
        int _slot = (c) % 3;                                                          \
        uint32_t _wd = sbase + SO_W +                                                 \
            (uint32_t)(_slot * 5120 + (t >> 2) * 80 + (t & 3) * 16);                  \
        CPA16(_wd, Wq + (size_t)(c) * 1024 + t * 4);                                  \
        if (t < 8)                                                                    \
            CPA16(sbase + SO_IDX + _slot * 128 + t * 16, idx + (c) * 32 + t * 4);     \
        CPCOMMIT();                                                                   \
    } while (0)

    STAGE(c0);
    STAGE(c0 + 1);   // cpb >= 2 always

    // ---- load L/R into T[m][f] bf16 rows + ones/zero pair ----
    {
        int m = t & 127, half = t >> 7;
        const float* src;
        if (mode == 1) {
            src = Xin + (size_t)(half * BATCH + tile * 128 + m) * D;
        } else if (mode == 2) {
            int g = tile * 128 + m;
            int p = g & 31, bp = g >> 5;
            int tree = bp >> 10, b = bp & 1023;
            const int* tbl = tree ? right : left;
            int vi = __ldg(tbl + b * 64 + 2 * p + half);
            src = g_vocT + (size_t)vi * D;
        } else {
            int g = tile * 128 + m;
            int p = g % n_out, bp = g / n_out;
            src = Xin + (size_t)(bp * 2 * n_out + 2 * p + half) * D;
        }
        char* Td = smem + SO_T + m * 260 + half * 128;
#pragma unroll
        for (int it = 0; it < 16; it++) {
            float4 v = *(const float4*)(src + it * 4);
            if (mode == 2) {
                float4 bb = *(const float4*)(voc_b + it * 4);
                v.x += bb.x; v.y += bb.y; v.z += bb.z; v.w += bb.w;
            }
            *(uint32_t*)(Td + it * 8)     = pack_bf16(v.x, v.y);
            *(uint32_t*)(Td + it * 8 + 4) = pack_bf16(v.z, v.w);
        }
        if (t < 128) *(uint32_t*)(smem + SO_T + t * 260 + 256) = 0x00003F80u; // (1.0, 0)
    }

    const int l = t & 31, wid = t >> 5;
    const int qr = l >> 2, qc = l & 3;
    const int m0 = (wid & 3) * 32;
    const int n0 = (wid >> 2) * 32;
    const int mloc = t & 127;
    const int kh2 = (t >> 7) * 8;
    const char* Trow = smem + SO_T + mloc * 260;

    const int lt = l >> 3, lr = l & 7;
    const uint32_t a_lane = (uint32_t)((m0 + ((lt & 1) << 3) + lr) * 80 + ((lt >> 1) << 4));
    const uint32_t b_lane = (uint32_t)((n0 + ((lt >> 1) << 3) + lr) * 80 + ((lt & 1) << 4));

    float acc[2][4][4] = {};

#define AGEN(c)                                                                       \
    do {                                                                              \
        const int4* ix4 = (const int4*)(smem + SO_IDX + ((c) % 3) * 128) + (kh2 >> 1);\
        uint32_t* Ad = (uint32_t*)(smem + SO_A + ((c) & 1) * 10240) + mloc * 20 + kh2;\
        uint32_t w[8];                                                                \
        _Pragma("unroll")                                                             \
        for (int qq = 0; qq < 4; qq++) {                                              \
            int4 pp = ix4[qq];                                                        \
            unsigned short a0 = *(const unsigned short*)(Trow + pp.x);                \
            uint32_t bv0 = *(const uint32_t*)(Trow + pp.y);                           \
            unsigned short a1 = *(const unsigned short*)(Trow + pp.z);                \
            uint32_t bv1 = *(const uint32_t*)(Trow + pp.w);                           \
            uint32_t ad0, ad1;                                                        \
            asm("mov.b32 %0, {%1,%1};" : "=r"(ad0) : "h"(a0));                        \
            asm("mov.b32 %0, {%1,%1};" : "=r"(ad1) : "h"(a1));                        \
            asm("mul.rn.bf16x2 %0, %1, %2;" : "=r"(w[qq * 2])     : "r"(ad0), "r"(bv0)); \
            asm("mul.rn.bf16x2 %0, %1, %2;" : "=r"(w[qq * 2 + 1]) : "r"(ad1), "r"(bv1)); \
        }                                                                             \
        *(uint4*)Ad       = make_uint4(w[0], w[1], w[2], w[3]);                       \
        *(uint4*)(Ad + 4) = make_uint4(w[4], w[5], w[6], w[7]);                       \
    } while (0)

    CPWAIT(1);
    __syncthreads();
    AGEN(c0);

    for (int c = c0; c < c1; c++) {
        __syncthreads();
        if (c + 2 < c1) {
            STAGE(c + 2);
            CPWAIT(1);
        } else {
            CPWAIT(0);
        }
        if (c + 1 < c1) AGEN(c + 1);

        const uint32_t Ab = sbase + SO_A + (uint32_t)((c & 1) * 10240) + a_lane;
        const uint32_t Wb = sbase + SO_W + (uint32_t)((c % 3) * 5120) + b_lane;
#pragma unroll
        for (int ks = 0; ks < 2; ks++) {
            uint32_t a0[4], a1[4], b01[4], b23[4];
            LDSM4(a0, Ab + ks * 32);
            LDSM4(a1, Ab + 1280 + ks * 32);
            LDSM4(b01, Wb + ks * 32);
            LDSM4(b23, Wb + 1280 + ks * 32);
            mma16(acc[0][0], a0, b01[0], b01[1]);
            mma16(acc[0][1], a0, b01[2], b01[3]);
            mma16(acc[0][2], a0, b23[0], b23[1]);
            mma16(acc[0][3], a0, b23[2], b23[3]);
            mma16(acc[1][0], a1, b01[0], b01[1]);
            mma16(acc[1][1], a1, b01[2], b01[3]);
            mma16(acc[1][2], a1, b23[0], b23[1]);
            mma16(acc[1][3], a1, b23[2], b23[3]);
        }
    }

    // ---- write partials ----
#pragma unroll
    for (int mf = 0; mf < 2; mf++) {
#pragma unroll
        for (int nf = 0; nf < 4; nf++) {
            int row = m0 + mf * 16 + qr;
            int col = n0 + nf * 8 + qc * 2;
            float* a4 = acc[mf][nf];
            float* dst = outpart + (size_t)(s * ntiles + tile) * 8192 + row * 64 + col;
            *(float2*)dst = make_float2(a4[0], a4[1]);
            *(float2*)(dst + 8 * 64) = make_float2(a4[2], a4[3]);
        }
    }
#undef STAGE
#undef AGEN

    // ---- last-block-per-tile reduction ----
    __threadfence();
    if (t == 0) {
        int old = atomicAdd(&g_cnt[tile], 1);
        s_is_last = (old == split - 1) ? 1 : 0;
    }
    __syncthreads();
    if (!s_is_last) return;
    __threadfence();                       // acquire: other blocks' partials visible
    if (t == 0) g_cnt[tile] = 0;           // reset for next level / graph replay

    const float4* srcp = (const float4*)(outpart + (size_t)tile * 8192);
    size_t stride4 = (size_t)ntiles * 2048;

    if (mode != 1) {
        float4* dstx = (float4*)(Xout + (size_t)tile * 8192);
        for (int i4 = t; i4 < 2048; i4 += 256) {
            float4 v = srcp[i4];
            for (int sp = 1; sp < split; sp++) {
                float4 u = srcp[sp * stride4 + i4];
                v.x += u.x; v.y += u.y; v.z += u.z; v.w += u.w;
            }
            float4 bb = *(const float4*)(e_bias + (i4 & 15) * 4);
            v.x = tanhf(v.x + bb.x); v.y = tanhf(v.y + bb.y);
            v.z = tanhf(v.z + bb.z); v.w = tanhf(v.w + bb.w);
            dstx[i4] = v;
        }
    } else {
        float* actT = (float*)(smem + SO_T);   // [128 m][65] fits exactly in T region
        for (int i4 = t; i4 < 2048; i4 += 256) {
            float4 v = srcp[i4];
            for (int sp = 1; sp < split; sp++) {
                float4 u = srcp[sp * stride4 + i4];
                v.x += u.x; v.y += u.y; v.z += u.z; v.w += u.w;
            }
            float4 bb = *(const float4*)(e_bias + (i4 & 15) * 4);
            int m = i4 >> 4, e0 = (i4 & 15) * 4;
            float vv[4] = {v.x + bb.x, v.y + bb.y, v.z + bb.z, v.w + bb.w};
#pragma unroll
            for (int j = 0; j < 4; j++) {
                float a = vv[j];
                a = (a > 0.f) ? a : 0.01f * a;
                actT[m * 65 + e0 + j] = a;
            }
        }
        __syncthreads();
        if (t < 128) {
            int m = t;
            float lg[NREL];
#pragma unroll
            for (int c = 0; c < NREL; c++) {
                float ssum = sm_b[c];
#pragma unroll 8
                for (int e = 0; e < 64; e++) ssum += actT[m * 65 + e] * sm_w[c * 64 + e];
                lg[c] = ssum;
            }
            float mx = lg[0];
#pragma unroll
            for (int c = 1; c < NREL; c++) mx = fmaxf(mx, lg[c]);
            float sum = 0.f;
#pragma unroll
            for (int c = 0; c < NREL; c++) { lg[c] = expf(lg[c] - mx); sum += lg[c]; }
            float inv = 1.f / sum;
#pragma unroll
            for (int c = 0; c < NREL; c++) Xout[(tile * 128 + m) * NREL + c] = lg[c] * inv;
        }
    }
}

// -------- launcher --------
extern "C" void kernel_launch(void* const* d_in, const int* in_sizes, int n_in,
                              void* d_out, int out_size) {
    (void)in_sizes; (void)n_in; (void)out_size;
    const int*   left   = (const int*)d_in[0];
    const int*   right  = (const int*)d_in[1];
    const float* voc_w  = (const float*)d_in[2];
    const float* voc_b  = (const float*)d_in[3];
    const float* cps_w  = (const float*)d_in[4];
    const float* cps_b  = (const float*)d_in[5];
    const float* cpst_w = (const float*)d_in[6];
    const float* cpst_b = (const float*)d_in[7];
    const float* cpr_w  = (const float*)d_in[8];
    const float* cpr_b  = (const float*)d_in[9];
    const float* cprt_w = (const float*)d_in[10];
    const float* cprt_b = (const float*)d_in[11];
    const float* sm_w   = (const float*)d_in[12];
    const float* sm_b   = (const float*)d_in[13];
    float* out = (float*)d_out;

    float *XA, *XB, *bc, *bf, *pA, *pB;
    uint32_t *Wc2, *Wf2;
    int *idxC, *idxF;
    cudaGetSymbolAddress((void**)&XA, g_XA);
    cudaGetSymbolAddress((void**)&XB, g_XB);
    cudaGetSymbolAddress((void**)&Wc2, g_Wc2);
    cudaGetSymbolAddress((void**)&Wf2, g_Wf2);
    cudaGetSymbolAddress((void**)&bc, g_bc);
    cudaGetSymbolAddress((void**)&bf, g_bf);
    cudaGetSymbolAddress((void**)&pA, g_partA);
    cudaGetSymbolAddress((void**)&pB, g_partB);
    cudaGetSymbolAddress((void**)&idxC, g_idxC);
    cudaGetSymbolAddress((void**)&idxF, g_idxF);

    cudaFuncSetAttribute(k_gemm, cudaFuncAttributeMaxDynamicSharedMemorySize, SMEM_BYTES);

    k_transpose_voc<<<(VOC + 63) / 64, 256>>>(voc_w);
    k_prep<<<NCHC + NCHF + 3, 256>>>(cps_w, cps_b, cpst_w, cpst_b,
                                     cpr_w, cpr_b, cprt_w, cprt_b);

    // L1 (vocab gather): 512 tiles, split 2 -> pA, reduced -> XB
    k_gemm<<<1024, 256, SMEM_BYTES>>>(nullptr, pA, Wc2, idxC, bc,
                                      left, right, voc_b, XB, sm_w, sm_b,
                                      32, NCHC, 2, 512, 2);
    // L2: 256 tiles, split 5 -> pB, reduced -> XA
    k_gemm<<<1280, 256, SMEM_BYTES>>>(XB, pB, Wc2, idxC, bc,
                                      left, right, voc_b, XA, sm_w, sm_b,
                                      16, NCHC, 5, 256, 0);
    // L3: 128 tiles, split 2 -> pA, reduced -> XB
    k_gemm<<<256, 256, SMEM_BYTES>>>(XA, pA, Wc2, idxC, bc,
                                     left, right, voc_b, XB, sm_w, sm_b,
                                     8, NCHC, 2, 128, 0);
    // L4: 64 tiles, split 5 -> pB, reduced -> XA
    k_gemm<<<320, 256, SMEM_BYTES>>>(XB, pB, Wc2, idxC, bc,
                                     left, right, voc_b, XA, sm_w, sm_b,
                                     4, NCHC, 5, 64, 0);
    // L5: 32 tiles, split 10 -> pA, reduced -> XB
    k_gemm<<<320, 256, SMEM_BYTES>>>(XA, pA, Wc2, idxC, bc,
                                     left, right, voc_b, XB, sm_w, sm_b,
                                     2, NCHC, 10, 32, 0);
    // L6: 16 tiles, split 14 -> pB, reduced -> XA
    k_gemm<<<224, 256, SMEM_BYTES>>>(XB, pB, Wc2, idxC, bc,
                                     left, right, voc_b, XA, sm_w, sm_b,
                                     1, NCHC, 14, 16, 0);
    // final: 8 tiles, split 33 -> pA, reduced+softmax -> out
    k_gemm<<<264, 256, SMEM_BYTES>>>(XA, pA, Wf2, idxF, bf,
                                     left, right, voc_b, out, sm_w, sm_b,
                                     1, NCHF, 33, 8, 1);
}

// round 16
// speedup vs baseline: 2.0886x; 1.1244x over previous
#include <cuda_runtime.h>
#include <cuda_bf16.h>
#include <math.h>
#include <cstdint>

#define BATCH 1024
#define D     64
#define VOC   50000
#define NREL  7
#define KC    2240      // compose: 2112 padded-triangular + 128 linear
#define NCHC  70
#define KF    4224      // final: 4096 kron + 128 linear
#define NCHF  132

// smem byte layout (total 69632 B -> 3 CTAs/SM)
#define SO_IDX 0           // 3 x 128 B idx slots
#define SO_T   512         // T bf16 [128 m][260 B]; reused as actT[128][65] f32
#define SO_A   33792       // 2 x (128 m x 80 B)
#define SO_W   54272       // 3 x (64 e x 80 B)
#define SMEM_BYTES 69632

// -------- device scratch --------
__device__ uint32_t g_vocT2[VOC * 32];    // bf16 pairs, voc_b pre-added (6.4 MB)
__device__ uint32_t g_XA2[2 * BATCH * 32 * 32];  // bf16 node rows (8 MB)
__device__ uint32_t g_XB2[2 * BATCH * 32 * 32];
__device__ uint32_t g_Wc2[NCHC * 1024];   // bf16x2 W chunks [c][e*16 + k2]
__device__ uint32_t g_Wf2[NCHF * 1024];
__device__ int      g_idxC[KC];           // per PAIR: (a_off, b_off) byte offsets
__device__ int      g_idxF[KF];
__device__ float    g_bc[D];
__device__ float    g_bf[D];
__device__ float    g_partA[1024 * 8192];
__device__ float    g_partB[1280 * 8192];
__device__ int      g_cnt[512];           // per-tile arrival counters (self-resetting)

// -------- PTX helpers --------
__device__ __forceinline__ uint32_t s2u(const void* p) {
    uint32_t a;
    asm("{.reg .u64 t; cvta.to.shared.u64 t, %1; cvt.u32.u64 %0, t;}" : "=r"(a) : "l"(p));
    return a;
}
__device__ __forceinline__ void mma16(float* d, const uint32_t* a, uint32_t b0, uint32_t b1) {
    asm volatile(
        "mma.sync.aligned.m16n8k16.row.col.f32.bf16.bf16.f32 "
        "{%0,%1,%2,%3},{%4,%5,%6,%7},{%8,%9},{%0,%1,%2,%3};"
        : "+f"(d[0]), "+f"(d[1]), "+f"(d[2]), "+f"(d[3])
        : "r"(a[0]), "r"(a[1]), "r"(a[2]), "r"(a[3]), "r"(b0), "r"(b1));
}
__device__ __forceinline__ uint32_t pack_bf16(float lo, float hi) {
    uint32_t d;
    asm("cvt.rn.bf16x2.f32 %0, %1, %2;" : "=r"(d) : "f"(hi), "f"(lo));
    return d;
}
#define LDSM4(R, addr)                                                        \
    asm volatile("ldmatrix.sync.aligned.m8n8.x4.shared.b16 {%0,%1,%2,%3}, [%4];" \
        : "=r"((R)[0]), "=r"((R)[1]), "=r"((R)[2]), "=r"((R)[3]) : "r"(addr))
#define CPA16(dst, src) \
    asm volatile("cp.async.ca.shared.global [%0], [%1], 16;" :: "r"(dst), "l"(src))
#define CPCOMMIT() asm volatile("cp.async.commit_group;")
#define CPWAIT(n)  asm volatile("cp.async.wait_group %0;" :: "n"(n) : "memory")

// -------- vocab transpose: (64, 50000) -> bf16 rows with voc_b pre-added --------
__global__ void k_transpose_voc(const float* __restrict__ voc_w,
                                const float* __restrict__ voc_b) {
    __shared__ float tile[64][65];
    int v0 = blockIdx.x * 64;
    for (int idx = threadIdx.x; idx < 64 * 64; idx += 256) {
        int d = idx >> 6, vv = idx & 63;
        int v = v0 + vv;
        tile[vv][d] = (v < VOC) ? voc_w[d * VOC + v] : 0.f;
    }
    __syncthreads();
    for (int idx = threadIdx.x; idx < 64 * 32; idx += 256) {
        int vv = idx >> 5, w = idx & 31;
        int v = v0 + vv;
        if (v < VOC) {
            float a = tile[vv][2 * w]     + voc_b[2 * w];
            float b = tile[vv][2 * w + 1] + voc_b[2 * w + 1];
            g_vocT2[v * 32 + w] = pack_bf16(a, b);
        }
    }
}

// -------- padded-triangular enumeration --------
__device__ __forceinline__ int startP(int i) {
    int m = i >> 1;
    return (i & 1) ? 2 * (m + 1) * (m + 1) : 2 * m * (m + 1);
}
__device__ __forceinline__ int rowP(int k) {
    int i = (int)sqrtf(2.f * (float)k + 1.f);
    if (i > 63) i = 63;
    while (startP(i) > k) i--;
    while (i < 63 && startP(i + 1) <= k) i++;
    return i;
}
__device__ __forceinline__ float wcomp(const float* cpst_w, const float* cps_w, int k, int e) {
    if (k < 2112) {
        int i = rowP(k);
        int j = k - startP(i);
        if (j < i)  return cpst_w[e * 4096 + i * 64 + j] + cpst_w[e * 4096 + j * 64 + i];
        if (j == i) return cpst_w[e * 4096 + i * 65];
        return 0.f;     // pad slot
    }
    return cps_w[e * 128 + (k - 2112)];
}

__global__ void k_prep(const float* __restrict__ cps_w,  const float* __restrict__ cps_b,
                       const float* __restrict__ cpst_w, const float* __restrict__ cpst_b,
                       const float* __restrict__ cpr_w,  const float* __restrict__ cpr_b,
                       const float* __restrict__ cprt_w, const float* __restrict__ cprt_b) {
    int blk = blockIdx.x, t = threadIdx.x;
    if (blk < NCHC) {                        // compose W chunks [e][k2]
        int c = blk;
        for (int u = t; u < 1024; u += 256) {
            int e = u >> 4, k2 = u & 15;
            int k = c * 32 + 2 * k2;
            g_Wc2[c * 1024 + u] = pack_bf16(wcomp(cpst_w, cps_w, k, e),
                                            wcomp(cpst_w, cps_w, k + 1, e));
        }
    } else if (blk < NCHC + NCHF) {          // final W chunks [e][k2]
        int c = blk - NCHC;
        for (int u = t; u < 1024; u += 256) {
            int e = u >> 4, k2 = u & 15;
            int k = c * 32 + 2 * k2;
            float v0 = (k < 4096) ? cprt_w[e * 4096 + k] : cpr_w[e * 128 + (k - 4096)];
            float v1 = (k + 1 < 4096) ? cprt_w[e * 4096 + k + 1] : cpr_w[e * 128 + (k + 1 - 4096)];
            g_Wf2[c * 1024 + u] = pack_bf16(v0, v1);
        }
    } else if (blk == NCHC + NCHF) {         // biases
        if (t < D) {
            g_bc[t] = cps_b[t] + cpst_b[t];
            g_bf[t] = cpr_b[t] + cprt_b[t];
        }
    } else if (blk == NCHC + NCHF + 1) {     // compose idx
        for (int p = t; p < KC / 2; p += 256) {
            int k = 2 * p;
            int a_off, b_off;
            if (k < 2112) {
                int i = rowP(k);
                a_off = i * 2;
                b_off = (k - startP(i)) * 2;
            } else {
                a_off = 128 * 2;
                b_off = (k - 2112) * 2;
            }
            g_idxC[p * 2] = a_off;
            g_idxC[p * 2 + 1] = b_off;
        }
    } else {                                 // final idx
        for (int p = t; p < KF / 2; p += 256) {
            int k = 2 * p;
            int a_off, b_off;
            if (k < 4096) {
                a_off = (k >> 6) * 2;
                b_off = (64 + (k & 63)) * 2;
            } else {
                a_off = 128 * 2;
                b_off = (k - 4096) * 2;
            }
            g_idxF[p * 2] = a_off;
            g_idxF[p * 2 + 1] = b_off;
        }
    }
}

// -------- pipelined bf16 tensor GEMM level + fused last-block reduction --------
// mode: 0 compose, 1 final, 2 level1 (vocab gather)
__global__ void __launch_bounds__(256, 3) k_gemm(const uint32_t* __restrict__ Xin,
                                                 float* __restrict__ outpart,
                                                 const uint32_t* __restrict__ Wq,
                                                 const int* __restrict__ idx,
                                                 const float* __restrict__ e_bias,
                                                 const int* __restrict__ left,
                                                 const int* __restrict__ right,
                                                 uint32_t* __restrict__ Xout_bf,
                                                 float* __restrict__ final_out,
                                                 const float* __restrict__ sm_w,
                                                 const float* __restrict__ sm_b,
                                                 int n_out, int nchunks, int split,
                                                 int ntiles, int mode) {
    extern __shared__ char smem[];
    __shared__ int s_is_last;
    const uint32_t sbase = s2u(smem);
    const int t = threadIdx.x;
    const int s = blockIdx.x % split;
    const int tile = blockIdx.x / split;
    const int cpb = nchunks / split;
    const int c0 = s * cpb, c1 = c0 + cpb;

#define STAGE(c)                                                                      \
    do {                                                                              \
        int _slot = (c) % 3;                                                          \
        uint32_t _wd = sbase + SO_W +                                                 \
            (uint32_t)(_slot * 5120 + (t >> 2) * 80 + (t & 3) * 16);                  \
        CPA16(_wd, Wq + (size_t)(c) * 1024 + t * 4);                                  \
        if (t < 8)                                                                    \
            CPA16(sbase + SO_IDX + _slot * 128 + t * 16, idx + (c) * 32 + t * 4);     \
        CPCOMMIT();                                                                   \
    } while (0)

    STAGE(c0);
    STAGE(c0 + 1);   // cpb >= 2 always

    // ---- copy L/R bf16 rows into T[m][f] + ones/zero pair ----
    {
        int m = t & 127, half = t >> 7;
        const uint32_t* srcw;
        if (mode == 1) {
            srcw = Xin + (size_t)(half * BATCH + tile * 128 + m) * 32;
        } else if (mode == 2) {
            int g = tile * 128 + m;
            int p = g & 31, bp = g >> 5;
            int tree = bp >> 10, b = bp & 1023;
            const int* tbl = tree ? right : left;
            int vi = __ldg(tbl + b * 64 + 2 * p + half);
            srcw = g_vocT2 + (size_t)vi * 32;
        } else {
            int g = tile * 128 + m;
            int p = g % n_out, bp = g / n_out;
            srcw = Xin + (size_t)(bp * 2 * n_out + 2 * p + half) * 32;
        }
        uint32_t* Td = (uint32_t*)(smem + SO_T + m * 260 + half * 128);
#pragma unroll
        for (int it = 0; it < 8; it++) {
            uint4 v = *(const uint4*)(srcw + it * 4);
            Td[it * 4] = v.x; Td[it * 4 + 1] = v.y;
            Td[it * 4 + 2] = v.z; Td[it * 4 + 3] = v.w;
        }
        if (t < 128) *(uint32_t*)(smem + SO_T + t * 260 + 256) = 0x00003F80u; // (1.0, 0)
    }

    const int l = t & 31, wid = t >> 5;
    const int qr = l >> 2, qc = l & 3;
    const int m0 = (wid & 3) * 32;
    const int n0 = (wid >> 2) * 32;
    const int mloc = t & 127;
    const int kh2 = (t >> 7) * 8;
    const char* Trow = smem + SO_T + mloc * 260;

    const int lt = l >> 3, lr = l & 7;
    const uint32_t a_lane = (uint32_t)((m0 + ((lt & 1) << 3) + lr) * 80 + ((lt >> 1) << 4));
    const uint32_t b_lane = (uint32_t)((n0 + ((lt >> 1) << 3) + lr) * 80 + ((lt & 1) << 4));

    float acc[2][4][4] = {};

#define AGEN(c)                                                                       \
    do {                                                                              \
        const int4* ix4 = (const int4*)(smem + SO_IDX + ((c) % 3) * 128) + (kh2 >> 1);\
        uint32_t* Ad = (uint32_t*)(smem + SO_A + ((c) & 1) * 10240) + mloc * 20 + kh2;\
        uint32_t w[8];                                                                \
        _Pragma("unroll")                                                             \
        for (int qq = 0; qq < 4; qq++) {                                              \
            int4 pp = ix4[qq];                                                        \
            unsigned short a0 = *(const unsigned short*)(Trow + pp.x);                \
            uint32_t bv0 = *(const uint32_t*)(Trow + pp.y);                           \
            unsigned short a1 = *(const unsigned short*)(Trow + pp.z);                \
            uint32_t bv1 = *(const uint32_t*)(Trow + pp.w);                           \
            uint32_t ad0, ad1;                                                        \
            asm("mov.b32 %0, {%1,%1};" : "=r"(ad0) : "h"(a0));                        \
            asm("mov.b32 %0, {%1,%1};" : "=r"(ad1) : "h"(a1));                        \
            asm("mul.rn.bf16x2 %0, %1, %2;" : "=r"(w[qq * 2])     : "r"(ad0), "r"(bv0)); \
            asm("mul.rn.bf16x2 %0, %1, %2;" : "=r"(w[qq * 2 + 1]) : "r"(ad1), "r"(bv1)); \
        }                                                                             \
        *(uint4*)Ad       = make_uint4(w[0], w[1], w[2], w[3]);                       \
        *(uint4*)(Ad + 4) = make_uint4(w[4], w[5], w[6], w[7]);                       \
    } while (0)

    CPWAIT(1);
    __syncthreads();
    AGEN(c0);

    for (int c = c0; c < c1; c++) {
        __syncthreads();
        if (c + 2 < c1) {
            STAGE(c + 2);
            CPWAIT(1);
        } else {
            CPWAIT(0);
        }
        if (c + 1 < c1) AGEN(c + 1);

        const uint32_t Ab = sbase + SO_A + (uint32_t)((c & 1) * 10240) + a_lane;
        const uint32_t Wb = sbase + SO_W + (uint32_t)((c % 3) * 5120) + b_lane;
#pragma unroll
        for (int ks = 0; ks < 2; ks++) {
            uint32_t a0[4], a1[4], b01[4], b23[4];
            LDSM4(a0, Ab + ks * 32);
            LDSM4(a1, Ab + 1280 + ks * 32);
            LDSM4(b01, Wb + ks * 32);
            LDSM4(b23, Wb + 1280 + ks * 32);
            mma16(acc[0][0], a0, b01[0], b01[1]);
            mma16(acc[0][1], a0, b01[2], b01[3]);
            mma16(acc[0][2], a0, b23[0], b23[1]);
            mma16(acc[0][3], a0, b23[2], b23[3]);
            mma16(acc[1][0], a1, b01[0], b01[1]);
            mma16(acc[1][1], a1, b01[2], b01[3]);
            mma16(acc[1][2], a1, b23[0], b23[1]);
            mma16(acc[1][3], a1, b23[2], b23[3]);
        }
    }

    // ---- write partials ----
#pragma unroll
    for (int mf = 0; mf < 2; mf++) {
#pragma unroll
        for (int nf = 0; nf < 4; nf++) {
            int row = m0 + mf * 16 + qr;
            int col = n0 + nf * 8 + qc * 2;
            float* a4 = acc[mf][nf];
            float* dst = outpart + (size_t)(s * ntiles + tile) * 8192 + row * 64 + col;
            *(float2*)dst = make_float2(a4[0], a4[1]);
            *(float2*)(dst + 8 * 64) = make_float2(a4[2], a4[3]);
        }
    }
#undef STAGE
#undef AGEN

    // ---- last-block-per-tile reduction ----
    __threadfence();
    if (t == 0) {
        int old = atomicAdd(&g_cnt[tile], 1);
        s_is_last = (old == split - 1) ? 1 : 0;
    }
    __syncthreads();
    if (!s_is_last) return;
    __threadfence();                       // acquire: other blocks' partials visible
    if (t == 0) g_cnt[tile] = 0;           // reset for next level / graph replay

    const float4* srcp = (const float4*)(outpart + (size_t)tile * 8192);
    size_t stride4 = (size_t)ntiles * 2048;

    if (mode != 1) {
        uint32_t* dstx = Xout_bf + (size_t)tile * 128 * 32;
        for (int i4 = t; i4 < 2048; i4 += 256) {
            float4 v = srcp[i4];
            for (int sp = 1; sp < split; sp++) {
                float4 u = srcp[sp * stride4 + i4];
                v.x += u.x; v.y += u.y; v.z += u.z; v.w += u.w;
            }
            float4 bb = *(const float4*)(e_bias + (i4 & 15) * 4);
            uint32_t w0 = pack_bf16(tanhf(v.x + bb.x), tanhf(v.y + bb.y));
            uint32_t w1 = pack_bf16(tanhf(v.z + bb.z), tanhf(v.w + bb.w));
            int m = i4 >> 4, f4 = i4 & 15;
            *(uint2*)(dstx + m * 32 + f4 * 2) = make_uint2(w0, w1);
        }
    } else {
        float* actT = (float*)(smem + SO_T);   // [128 m][65] fits in T region
        for (int i4 = t; i4 < 2048; i4 += 256) {
            float4 v = srcp[i4];
            for (int sp = 1; sp < split; sp++) {
                float4 u = srcp[sp * stride4 + i4];
                v.x += u.x; v.y += u.y; v.z += u.z; v.w += u.w;
            }
            float4 bb = *(const float4*)(e_bias + (i4 & 15) * 4);
            int m = i4 >> 4, e0 = (i4 & 15) * 4;
            float vv[4] = {v.x + bb.x, v.y + bb.y, v.z + bb.z, v.w + bb.w};
#pragma unroll
            for (int j = 0; j < 4; j++) {
                float a = vv[j];
                a = (a > 0.f) ? a : 0.01f * a;
                actT[m * 65 + e0 + j] = a;
            }
        }
        __syncthreads();
        if (t < 128) {
            int m = t;
            float lg[NREL];
#pragma unroll
            for (int c = 0; c < NREL; c++) {
                float ssum = sm_b[c];
#pragma unroll 8
                for (int e = 0; e < 64; e++) ssum += actT[m * 65 + e] * sm_w[c * 64 + e];
                lg[c] = ssum;
            }
            float mx = lg[0];
#pragma unroll
            for (int c = 1; c < NREL; c++) mx = fmaxf(mx, lg[c]);
            float sum = 0.f;
#pragma unroll
            for (int c = 0; c < NREL; c++) { lg[c] = expf(lg[c] - mx); sum += lg[c]; }
            float inv = 1.f / sum;
#pragma unroll
            for (int c = 0; c < NREL; c++) final_out[(tile * 128 + m) * NREL + c] = lg[c] * inv;
        }
    }
}

// -------- launcher --------
extern "C" void kernel_launch(void* const* d_in, const int* in_sizes, int n_in,
                              void* d_out, int out_size) {
    (void)in_sizes; (void)n_in; (void)out_size;
    const int*   left   = (const int*)d_in[0];
    const int*   right  = (const int*)d_in[1];
    const float* voc_w  = (const float*)d_in[2];
    const float* voc_b  = (const float*)d_in[3];
    const float* cps_w  = (const float*)d_in[4];
    const float* cps_b  = (const float*)d_in[5];
    const float* cpst_w = (const float*)d_in[6];
    const float* cpst_b = (const float*)d_in[7];
    const float* cpr_w  = (const float*)d_in[8];
    const float* cpr_b  = (const float*)d_in[9];
    const float* cprt_w = (const float*)d_in[10];
    const float* cprt_b = (const float*)d_in[11];
    const float* sm_w   = (const float*)d_in[12];
    const float* sm_b   = (const float*)d_in[13];
    float* out = (float*)d_out;

    float *bc, *bf, *pA, *pB;
    uint32_t *XA2, *XB2, *Wc2, *Wf2;
    int *idxC, *idxF;
    cudaGetSymbolAddress((void**)&XA2, g_XA2);
    cudaGetSymbolAddress((void**)&XB2, g_XB2);
    cudaGetSymbolAddress((void**)&Wc2, g_Wc2);
    cudaGetSymbolAddress((void**)&Wf2, g_Wf2);
    cudaGetSymbolAddress((void**)&bc, g_bc);
    cudaGetSymbolAddress((void**)&bf, g_bf);
    cudaGetSymbolAddress((void**)&pA, g_partA);
    cudaGetSymbolAddress((void**)&pB, g_partB);
    cudaGetSymbolAddress((void**)&idxC, g_idxC);
    cudaGetSymbolAddress((void**)&idxF, g_idxF);

    cudaFuncSetAttribute(k_gemm, cudaFuncAttributeMaxDynamicSharedMemorySize, SMEM_BYTES);

    k_transpose_voc<<<(VOC + 63) / 64, 256>>>(voc_w, voc_b);
    k_prep<<<NCHC + NCHF + 3, 256>>>(cps_w, cps_b, cpst_w, cpst_b,
                                     cpr_w, cpr_b, cprt_w, cprt_b);

    // L1 (vocab gather): 512 tiles, split 2 -> pA, reduced -> XB2
    k_gemm<<<1024, 256, SMEM_BYTES>>>(nullptr, pA, Wc2, idxC, bc,
                                      left, right, XB2, out, sm_w, sm_b,
                                      32, NCHC, 2, 512, 2);
    // L2: 256 tiles, split 5 -> pB, reduced -> XA2
    k_gemm<<<1280, 256, SMEM_BYTES>>>(XB2, pB, Wc2, idxC, bc,
                                      left, right, XA2, out, sm_w, sm_b,
                                      16, NCHC, 5, 256, 0);
    // L3: 128 tiles, split 2 -> pA, reduced -> XB2
    k_gemm<<<256, 256, SMEM_BYTES>>>(XA2, pA, Wc2, idxC, bc,
                                     left, right, XB2, out, sm_w, sm_b,
                                     8, NCHC, 2, 128, 0);
    // L4: 64 tiles, split 5 -> pB, reduced -> XA2
    k_gemm<<<320, 256, SMEM_BYTES>>>(XB2, pB, Wc2, idxC, bc,
                                     left, right, XA2, out, sm_w, sm_b,
                                     4, NCHC, 5, 64, 0);
    // L5: 32 tiles, split 10 -> pA, reduced -> XB2
    k_gemm<<<320, 256, SMEM_BYTES>>>(XA2, pA, Wc2, idxC, bc,
                                     left, right, XB2, out, sm_w, sm_b,
                                     2, NCHC, 10, 32, 0);
    // L6: 16 tiles, split 14 -> pB, reduced -> XA2
    k_gemm<<<224, 256, SMEM_BYTES>>>(XB2, pB, Wc2, idxC, bc,
                                     left, right, XA2, out, sm_w, sm_b,
                                     1, NCHC, 14, 16, 0);
    // final: 8 tiles, split 33 -> pA, reduced+softmax -> out
    k_gemm<<<264, 256, SMEM_BYTES>>>(XA2, pA, Wf2, idxF, bf,
                                     left, right, nullptr, out, sm_w, sm_b,
                                     1, NCHF, 33, 8, 1);
}

// round 17
// speedup vs baseline: 2.1076x; 1.0091x over previous
#include <cuda_runtime.h>
#include <cuda_bf16.h>
#include <math.h>
#include <cstdint>

#define BATCH 1024
#define D     64
#define VOC   50000
#define NREL  7
#define KC    2240      // compose: 2112 padded-triangular + 128 linear
#define NCHC  70
#define KF    4224      // final: 4096 kron + 128 linear
#define NCHF  132

// smem byte layout (total 69632 B -> 3 CTAs/SM)
#define SO_IDX 0           // 3 x 128 B idx slots
#define SO_T   512         // T bf16 [128 m][260 B]; reused as actT[128][65] f32
#define SO_A   33792       // 2 x (128 m x 80 B)
#define SO_W   54272       // 3 x (64 e x 80 B)
#define SMEM_BYTES 69632

// -------- device scratch --------
__device__ uint32_t g_vocT2[VOC * 32];    // bf16 pairs, voc_b pre-added (6.4 MB)
__device__ uint32_t g_XA2[2 * BATCH * 32 * 32];  // bf16 node rows
__device__ uint32_t g_XB2[2 * BATCH * 32 * 32];
__device__ uint32_t g_Wc2[NCHC * 1024];   // bf16x2 W chunks [c][e*16 + k2]
__device__ uint32_t g_Wf2[NCHF * 1024];
__device__ int      g_idxC[KC];           // per PAIR: (a_off, b_off) byte offsets
__device__ int      g_idxF[KF];
__device__ float    g_bc[D];
__device__ float    g_bf[D];
__device__ float    g_partA[1024 * 8192];
__device__ float    g_partB[1280 * 8192];
__device__ int      g_cnt[512];           // per-tile arrival counters (self-resetting)

// -------- PTX helpers --------
__device__ __forceinline__ uint32_t s2u(const void* p) {
    uint32_t a;
    asm("{.reg .u64 t; cvta.to.shared.u64 t, %1; cvt.u32.u64 %0, t;}" : "=r"(a) : "l"(p));
    return a;
}
__device__ __forceinline__ void mma16(float* d, const uint32_t* a, uint32_t b0, uint32_t b1) {
    asm volatile(
        "mma.sync.aligned.m16n8k16.row.col.f32.bf16.bf16.f32 "
        "{%0,%1,%2,%3},{%4,%5,%6,%7},{%8,%9},{%0,%1,%2,%3};"
        : "+f"(d[0]), "+f"(d[1]), "+f"(d[2]), "+f"(d[3])
        : "r"(a[0]), "r"(a[1]), "r"(a[2]), "r"(a[3]), "r"(b0), "r"(b1));
}
__device__ __forceinline__ uint32_t pack_bf16(float lo, float hi) {
    uint32_t d;
    asm("cvt.rn.bf16x2.f32 %0, %1, %2;" : "=r"(d) : "f"(hi), "f"(lo));
    return d;
}
#define LDSM4(R, addr)                                                        \
    asm volatile("ldmatrix.sync.aligned.m8n8.x4.shared.b16 {%0,%1,%2,%3}, [%4];" \
        : "=r"((R)[0]), "=r"((R)[1]), "=r"((R)[2]), "=r"((R)[3]) : "r"(addr))
#define CPA16(dst, src) \
    asm volatile("cp.async.ca.shared.global [%0], [%1], 16;" :: "r"(dst), "l"(src))
#define CPCOMMIT() asm volatile("cp.async.commit_group;")
#define CPWAIT(n)  asm volatile("cp.async.wait_group %0;" :: "n"(n) : "memory")

// -------- vocab transpose: (64, 50000) -> bf16 rows with voc_b pre-added --------
__global__ void k_transpose_voc(const float* __restrict__ voc_w,
                                const float* __restrict__ voc_b) {
    __shared__ float tile[64][65];
    int v0 = blockIdx.x * 64;
    for (int idx = threadIdx.x; idx < 64 * 64; idx += 256) {
        int d = idx >> 6, vv = idx & 63;
        int v = v0 + vv;
        tile[vv][d] = (v < VOC) ? voc_w[d * VOC + v] : 0.f;
    }
    __syncthreads();
    for (int idx = threadIdx.x; idx < 64 * 32; idx += 256) {
        int vv = idx >> 5, w = idx & 31;
        int v = v0 + vv;
        if (v < VOC) {
            float a = tile[vv][2 * w]     + voc_b[2 * w];
            float b = tile[vv][2 * w + 1] + voc_b[2 * w + 1];
            g_vocT2[v * 32 + w] = pack_bf16(a, b);
        }
    }
}

// -------- padded-triangular enumeration --------
__device__ __forceinline__ int startP(int i) {
    int m = i >> 1;
    return (i & 1) ? 2 * (m + 1) * (m + 1) : 2 * m * (m + 1);
}
__device__ __forceinline__ int rowP(int k) {
    int i = (int)sqrtf(2.f * (float)k + 1.f);
    if (i > 63) i = 63;
    while (startP(i) > k) i--;
    while (i < 63 && startP(i + 1) <= k) i++;
    return i;
}
__device__ __forceinline__ float wcomp(const float* cpst_w, const float* cps_w, int k, int e) {
    if (k < 2112) {
        int i = rowP(k);
        int j = k - startP(i);
        if (j < i)  return cpst_w[e * 4096 + i * 64 + j] + cpst_w[e * 4096 + j * 64 + i];
        if (j == i) return cpst_w[e * 4096 + i * 65];
        return 0.f;     // pad slot
    }
    return cps_w[e * 128 + (k - 2112)];
}

__global__ void k_prep(const float* __restrict__ cps_w,  const float* __restrict__ cps_b,
                       const float* __restrict__ cpst_w, const float* __restrict__ cpst_b,
                       const float* __restrict__ cpr_w,  const float* __restrict__ cpr_b,
                       const float* __restrict__ cprt_w, const float* __restrict__ cprt_b) {
    int blk = blockIdx.x, t = threadIdx.x;
    if (blk < NCHC) {                        // compose W chunks [e][k2]
        int c = blk;
        for (int u = t; u < 1024; u += 256) {
            int e = u >> 4, k2 = u & 15;
            int k = c * 32 + 2 * k2;
            g_Wc2[c * 1024 + u] = pack_bf16(wcomp(cpst_w, cps_w, k, e),
                                            wcomp(cpst_w, cps_w, k + 1, e));
        }
    } else if (blk < NCHC + NCHF) {          // final W chunks [e][k2]
        int c = blk - NCHC;
        for (int u = t; u < 1024; u += 256) {
            int e = u >> 4, k2 = u & 15;
            int k = c * 32 + 2 * k2;
            float v0 = (k < 4096) ? cprt_w[e * 4096 + k] : cpr_w[e * 128 + (k - 4096)];
            float v1 = (k + 1 < 4096) ? cprt_w[e * 4096 + k + 1] : cpr_w[e * 128 + (k + 1 - 4096)];
            g_Wf2[c * 1024 + u] = pack_bf16(v0, v1);
        }
    } else if (blk == NCHC + NCHF) {         // biases
        if (t < D) {
            g_bc[t] = cps_b[t] + cpst_b[t];
            g_bf[t] = cpr_b[t] + cprt_b[t];
        }
    } else if (blk == NCHC + NCHF + 1) {     // compose idx
        for (int p = t; p < KC / 2; p += 256) {
            int k = 2 * p;
            int a_off, b_off;
            if (k < 2112) {
                int i = rowP(k);
                a_off = i * 2;
                b_off = (k - startP(i)) * 2;
            } else {
                a_off = 128 * 2;
                b_off = (k - 2112) * 2;
            }
            g_idxC[p * 2] = a_off;
            g_idxC[p * 2 + 1] = b_off;
        }
    } else {                                 // final idx
        for (int p = t; p < KF / 2; p += 256) {
            int k = 2 * p;
            int a_off, b_off;
            if (k < 4096) {
                a_off = (k >> 6) * 2;
                b_off = (64 + (k & 63)) * 2;
            } else {
                a_off = 128 * 2;
                b_off = (k - 4096) * 2;
            }
            g_idxF[p * 2] = a_off;
            g_idxF[p * 2 + 1] = b_off;
        }
    }
}

// -------- pipelined bf16 tensor GEMM level + fused last-block reduction --------
// mode: 0 compose, 1 final, 2 level1 (vocab gather)
__global__ void __launch_bounds__(256, 3) k_gemm(const uint32_t* __restrict__ Xin,
                                                 float* __restrict__ outpart,
                                                 const uint32_t* __restrict__ Wq,
                                                 const int* __restrict__ idx,
                                                 const float* __restrict__ e_bias,
                                                 const int* __restrict__ left,
                                                 const int* __restrict__ right,
                                                 uint32_t* __restrict__ Xout_bf,
                                                 float* __restrict__ final_out,
                                                 const float* __restrict__ sm_w,
                                                 const float* __restrict__ sm_b,
                                                 int n_out, int nchunks, int split,
                                                 int ntiles, int mode) {
    extern __shared__ char smem[];
    __shared__ int s_is_last;
    const uint32_t sbase = s2u(smem);
    const int t = threadIdx.x;
    const int s = blockIdx.x % split;
    const int tile = blockIdx.x / split;
    const int cpb = nchunks / split;
    const int c0 = s * cpb, c1 = c0 + cpb;

#define STAGE(c)                                                                      \
    do {                                                                              \
        int _slot = (c) % 3;                                                          \
        uint32_t _wd = sbase + SO_W +                                                 \
            (uint32_t)(_slot * 5120 + (t >> 2) * 80 + (t & 3) * 16);                  \
        CPA16(_wd, Wq + (size_t)(c) * 1024 + t * 4);                                  \
        if (t < 8)                                                                    \
            CPA16(sbase + SO_IDX + _slot * 128 + t * 16, idx + (c) * 32 + t * 4);     \
        CPCOMMIT();                                                                   \
    } while (0)

    STAGE(c0);
    STAGE(c0 + 1);   // cpb >= 4 for all chosen splits

    // ---- copy L/R bf16 rows into T[m][f] + ones/zero pair ----
    {
        int m = t & 127, half = t >> 7;
        const uint32_t* srcw;
        if (mode == 1) {
            srcw = Xin + (size_t)(half * BATCH + tile * 128 + m) * 32;
        } else if (mode == 2) {
            int g = tile * 128 + m;
            int p = g & 31, bp = g >> 5;
            int tree = bp >> 10, b = bp & 1023;
            const int* tbl = tree ? right : left;
            int vi = __ldg(tbl + b * 64 + 2 * p + half);
            srcw = g_vocT2 + (size_t)vi * 32;
        } else {
            int g = tile * 128 + m;
            int p = g % n_out, bp = g / n_out;
            srcw = Xin + (size_t)(bp * 2 * n_out + 2 * p + half) * 32;
        }
        uint32_t* Td = (uint32_t*)(smem + SO_T + m * 260 + half * 128);
#pragma unroll
        for (int it = 0; it < 8; it++) {
            uint4 v = *(const uint4*)(srcw + it * 4);
            Td[it * 4] = v.x; Td[it * 4 + 1] = v.y;
            Td[it * 4 + 2] = v.z; Td[it * 4 + 3] = v.w;
        }
        if (t < 128) *(uint32_t*)(smem + SO_T + t * 260 + 256) = 0x00003F80u; // (1.0, 0)
    }

    const int l = t & 31, wid = t >> 5;
    const int qr = l >> 2, qc = l & 3;
    const int m0 = (wid & 3) * 32;
    const int n0 = (wid >> 2) * 32;
    const int mloc = t & 127;
    const int kh2 = (t >> 7) * 8;
    const char* Trow = smem + SO_T + mloc * 260;

    const int lt = l >> 3, lr = l & 7;
    const uint32_t a_lane = (uint32_t)((m0 + ((lt & 1) << 3) + lr) * 80 + ((lt >> 1) << 4));
    const uint32_t b_lane = (uint32_t)((n0 + ((lt >> 1) << 3) + lr) * 80 + ((lt & 1) << 4));

    float acc[2][4][4] = {};

#define AGEN(c)                                                                       \
    do {                                                                              \
        const int4* ix4 = (const int4*)(smem + SO_IDX + ((c) % 3) * 128) + (kh2 >> 1);\
        uint32_t* Ad = (uint32_t*)(smem + SO_A + ((c) & 1) * 10240) + mloc * 20 + kh2;\
        uint32_t w[8];                                                                \
        _Pragma("unroll")                                                             \
        for (int qq = 0; qq < 4; qq++) {                                              \
            int4 pp = ix4[qq];                                                        \
            unsigned short a0 = *(const unsigned short*)(Trow + pp.x);                \
            uint32_t bv0 = *(const uint32_t*)(Trow + pp.y);                           \
            unsigned short a1 = *(const unsigned short*)(Trow + pp.z);                \
            uint32_t bv1 = *(const uint32_t*)(Trow + pp.w);                           \
            uint32_t ad0, ad1;                                                        \
            asm("mov.b32 %0, {%1,%1};" : "=r"(ad0) : "h"(a0));                        \
            asm("mov.b32 %0, {%1,%1};" : "=r"(ad1) : "h"(a1));                        \
            asm("mul.rn.bf16x2 %0, %1, %2;" : "=r"(w[qq * 2])     : "r"(ad0), "r"(bv0)); \
            asm("mul.rn.bf16x2 %0, %1, %2;" : "=r"(w[qq * 2 + 1]) : "r"(ad1), "r"(bv1)); \
        }                                                                             \
        *(uint4*)Ad       = make_uint4(w[0], w[1], w[2], w[3]);                       \
        *(uint4*)(Ad + 4) = make_uint4(w[4], w[5], w[6], w[7]);                       \
    } while (0)

    CPWAIT(1);            // group c0 complete
    __syncthreads();
    AGEN(c0);

    for (int c = c0; c < c1; c++) {
        __syncthreads();  // publishes A(c) (AGEN of prev iter) and W(c) (drained prev iter)

        // ---- MMA(c) FIRST: its inputs are ready at the sync ----
        const uint32_t Ab = sbase + SO_A + (uint32_t)((c & 1) * 10240) + a_lane;
        const uint32_t Wb = sbase + SO_W + (uint32_t)((c % 3) * 5120) + b_lane;
#pragma unroll
        for (int ks = 0; ks < 2; ks++) {
            uint32_t a0[4], a1[4], b01[4], b23[4];
            LDSM4(a0, Ab + ks * 32);
            LDSM4(a1, Ab + 1280 + ks * 32);
            LDSM4(b01, Wb + ks * 32);
            LDSM4(b23, Wb + 1280 + ks * 32);
            mma16(acc[0][0], a0, b01[0], b01[1]);
            mma16(acc[0][1], a0, b01[2], b01[3]);
            mma16(acc[0][2], a0, b23[0], b23[1]);
            mma16(acc[0][3], a0, b23[2], b23[3]);
            mma16(acc[1][0], a1, b01[0], b01[1]);
            mma16(acc[1][1], a1, b01[2], b01[3]);
            mma16(acc[1][2], a1, b23[0], b23[1]);
            mma16(acc[1][3], a1, b23[2], b23[3]);
        }

        // ---- then prefetch + A-gen for later chunks (fills HMMA shadow) ----
        if (c + 2 < c1) {
            STAGE(c + 2);
            CPWAIT(1);    // group c+1 complete; c+2 in flight
        } else {
            CPWAIT(0);
        }
        if (c + 1 < c1) AGEN(c + 1);
    }

    // ---- write partials ----
#pragma unroll
    for (int mf = 0; mf < 2; mf++) {
#pragma unroll
        for (int nf = 0; nf < 4; nf++) {
            int row = m0 + mf * 16 + qr;
            int col = n0 + nf * 8 + qc * 2;
            float* a4 = acc[mf][nf];
            float* dst = outpart + (size_t)(s * ntiles + tile) * 8192 + row * 64 + col;
            *(float2*)dst = make_float2(a4[0], a4[1]);
            *(float2*)(dst + 8 * 64) = make_float2(a4[2], a4[3]);
        }
    }
#undef STAGE
#undef AGEN

    // ---- last-block-per-tile reduction ----
    __threadfence();
    if (t == 0) {
        int old = atomicAdd(&g_cnt[tile], 1);
        s_is_last = (old == split - 1) ? 1 : 0;
    }
    __syncthreads();
    if (!s_is_last) return;
    __threadfence();                       // acquire: other blocks' partials visible
    if (t == 0) g_cnt[tile] = 0;           // reset for next level / graph replay

    const float4* srcp = (const float4*)(outpart + (size_t)tile * 8192);
    size_t stride4 = (size_t)ntiles * 2048;

    if (mode != 1) {
        uint32_t* dstx = Xout_bf + (size_t)tile * 128 * 32;
        for (int i4 = t; i4 < 2048; i4 += 256) {
            float4 v = srcp[i4];
            for (int sp = 1; sp < split; sp++) {
                float4 u = srcp[sp * stride4 + i4];
                v.x += u.x; v.y += u.y; v.z += u.z; v.w += u.w;
            }
            float4 bb = *(const float4*)(e_bias + (i4 & 15) * 4);
            uint32_t w0 = pack_bf16(tanhf(v.x + bb.x), tanhf(v.y + bb.y));
            uint32_t w1 = pack_bf16(tanhf(v.z + bb.z), tanhf(v.w + bb.w));
            int m = i4 >> 4, f4 = i4 & 15;
            *(uint2*)(dstx + m * 32 + f4 * 2) = make_uint2(w0, w1);
        }
    } else {
        float* actT = (float*)(smem + SO_T);   // [128 m][65] fits in T region
        for (int i4 = t; i4 < 2048; i4 += 256) {
            float4 v = srcp[i4];
            for (int sp = 1; sp < split; sp++) {
                float4 u = srcp[sp * stride4 + i4];
                v.x += u.x; v.y += u.y; v.z += u.z; v.w += u.w;
            }
            float4 bb = *(const float4*)(e_bias + (i4 & 15) * 4);
            int m = i4 >> 4, e0 = (i4 & 15) * 4;
            float vv[4] = {v.x + bb.x, v.y + bb.y, v.z + bb.z, v.w + bb.w};
#pragma unroll
            for (int j = 0; j < 4; j++) {
                float a = vv[j];
                a = (a > 0.f) ? a : 0.01f * a;
                actT[m * 65 + e0 + j] = a;
            }
        }
        __syncthreads();
        if (t < 128) {
            int m = t;
            float lg[NREL];
#pragma unroll
            for (int c = 0; c < NREL; c++) {
                float ssum = sm_b[c];
#pragma unroll 8
                for (int e = 0; e < 64; e++) ssum += actT[m * 65 + e] * sm_w[c * 64 + e];
                lg[c] = ssum;
            }
            float mx = lg[0];
#pragma unroll
            for (int c = 1; c < NREL; c++) mx = fmaxf(mx, lg[c]);
            float sum = 0.f;
#pragma unroll
            for (int c = 0; c < NREL; c++) { lg[c] = expf(lg[c] - mx); sum += lg[c]; }
            float inv = 1.f / sum;
#pragma unroll
            for (int c = 0; c < NREL; c++) final_out[(tile * 128 + m) * NREL + c] = lg[c] * inv;
        }
    }
}

// -------- launcher --------
extern "C" void kernel_launch(void* const* d_in, const int* in_sizes, int n_in,
                              void* d_out, int out_size) {
    (void)in_sizes; (void)n_in; (void)out_size;
    const int*   left   = (const int*)d_in[0];
    const int*   right  = (const int*)d_in[1];
    const float* voc_w  = (const float*)d_in[2];
    const float* voc_b  = (const float*)d_in[3];
    const float* cps_w  = (const float*)d_in[4];
    const float* cps_b  = (const float*)d_in[5];
    const float* cpst_w = (const float*)d_in[6];
    const float* cpst_b = (const float*)d_in[7];
    const float* cpr_w  = (const float*)d_in[8];
    const float* cpr_b  = (const float*)d_in[9];
    const float* cprt_w = (const float*)d_in[10];
    const float* cprt_b = (const float*)d_in[11];
    const float* sm_w   = (const float*)d_in[12];
    const float* sm_b   = (const float*)d_in[13];
    float* out = (float*)d_out;

    float *bc, *bf, *pA, *pB;
    uint32_t *XA2, *XB2, *Wc2, *Wf2;
    int *idxC, *idxF;
    cudaGetSymbolAddress((void**)&XA2, g_XA2);
    cudaGetSymbolAddress((void**)&XB2, g_XB2);
    cudaGetSymbolAddress((void**)&Wc2, g_Wc2);
    cudaGetSymbolAddress((void**)&Wf2, g_Wf2);
    cudaGetSymbolAddress((void**)&bc, g_bc);
    cudaGetSymbolAddress((void**)&bf, g_bf);
    cudaGetSymbolAddress((void**)&pA, g_partA);
    cudaGetSymbolAddress((void**)&pB, g_partB);
    cudaGetSymbolAddress((void**)&idxC, g_idxC);
    cudaGetSymbolAddress((void**)&idxF, g_idxF);

    cudaFuncSetAttribute(k_gemm, cudaFuncAttributeMaxDynamicSharedMemorySize, SMEM_BYTES);

    k_transpose_voc<<<(VOC + 63) / 64, 256>>>(voc_w, voc_b);
    k_prep<<<NCHC + NCHF + 3, 256>>>(cps_w, cps_b, cpst_w, cpst_b,
                                     cpr_w, cpr_b, cprt_w, cprt_b);

    // L1 (vocab gather): 512 tiles, split 2 -> pA, reduced -> XB2
    k_gemm<<<1024, 256, SMEM_BYTES>>>(nullptr, pA, Wc2, idxC, bc,
                                      left, right, XB2, out, sm_w, sm_b,
                                      32, NCHC, 2, 512, 2);
    // L2: 256 tiles, split 5 -> pB, reduced -> XA2
    k_gemm<<<1280, 256, SMEM_BYTES>>>(XB2, pB, Wc2, idxC, bc,
                                      left, right, XA2, out, sm_w, sm_b,
                                      16, NCHC, 5, 256, 0);
    // L3: 128 tiles, split 2 -> pA, reduced -> XB2
    k_gemm<<<256, 256, SMEM_BYTES>>>(XA2, pA, Wc2, idxC, bc,
                                     left, right, XB2, out, sm_w, sm_b,
                                     8, NCHC, 2, 128, 0);
    // L4: 64 tiles, split 5 -> pB, reduced -> XA2
    k_gemm<<<320, 256, SMEM_BYTES>>>(XB2, pB, Wc2, idxC, bc,
                                     left, right, XA2, out, sm_w, sm_b,
                                     4, NCHC, 5, 64, 0);
    // L5: 32 tiles, split 10 -> pA, reduced -> XB2
    k_gemm<<<320, 256, SMEM_BYTES>>>(XA2, pA, Wc2, idxC, bc,
                                     left, right, XB2, out, sm_w, sm_b,
                                     2, NCHC, 10, 32, 0);
    // L6: 16 tiles, split 14 -> pB, reduced -> XA2
    k_gemm<<<224, 256, SMEM_BYTES>>>(XB2, pB, Wc2, idxC, bc,
                                     left, right, XA2, out, sm_w, sm_b,
                                     1, NCHC, 14, 16, 0);
    // final: 8 tiles, split 33 -> pA, reduced+softmax -> out
    k_gemm<<<264, 256, SMEM_BYTES>>>(XA2, pA, Wf2, idxF, bf,
                                     left, right, nullptr, out, sm_w, sm_b,
                                     1, NCHF, 33, 8, 1);
}